// round 8
// baseline (speedup 1.0000x reference)
#include <cuda_runtime.h>
#include <cuda_bf16.h>
#include <math.h>
#include <stdint.h>

// ---------------- problem constants ----------------
#define Bsz    64
#define Dm     768
#define Hn     12
#define DHd    64
#define Lnum   12
#define FFd    3072
#define NPRn   8
#define STOK   205
#define NPATCH 196
#define MTOK   (Bsz*STOK)     // 13120
#define MPATCH (Bsz*NPATCH)   // 12544 = 98*128
#define MPAD   13184          // 103*128 >= MTOK
#define K768E  2304           // 3*768 expanded K
#define KFFE   9216           // 3*3072 expanded K
#define NQKV   2304           // fused q|k|v output width

// ---------------- static device scratch ----------------
__device__ float g_x[MPAD*Dm];
__device__ float g_qkv[(size_t)MPAD*NQKV];              // packed q|k|v fp32
__device__ float         g_bqkv[(size_t)Lnum*NQKV];
__device__ __nv_bfloat16 g_ae1[(size_t)MPAD*K768E];     // expanded activations
__device__ __nv_bfloat16 g_ae2[(size_t)MPAD*KFFE];      // expanded MLP hidden
__device__ __nv_bfloat16 g_wqkv[(size_t)Lnum*NQKV*K768E];
__device__ __nv_bfloat16 g_wo[(size_t)Lnum*Dm*K768E];
__device__ __nv_bfloat16 g_w1[(size_t)Lnum*FFd*K768E];
__device__ __nv_bfloat16 g_w2[(size_t)Lnum*Dm*KFFE];
__device__ __nv_bfloat16 g_wp[(size_t)Dm*K768E];

// ---------------- helpers ----------------
__device__ __forceinline__ float qgelu(float x) {
    return x / (1.f + expf(-1.702f * x));
}
__device__ __forceinline__ void split_bf(float v, __nv_bfloat16& hi, __nv_bfloat16& lo) {
    hi = __float2bfloat16(v);
    lo = __float2bfloat16(v - __bfloat162float(hi));
}
__device__ __forceinline__ void cp16(void* s, const void* g) {
    unsigned sa = (unsigned)__cvta_generic_to_shared(s);
    asm volatile("cp.async.ca.shared.global [%0], [%1], 16;\n" :: "r"(sa), "l"(g));
}
__device__ __forceinline__ void ldm4(unsigned* r, const __nv_bfloat16* p) {
    unsigned s = (unsigned)__cvta_generic_to_shared(p);
    asm volatile("ldmatrix.sync.aligned.m8n8.x4.shared.b16 {%0,%1,%2,%3}, [%4];"
                 : "=r"(r[0]), "=r"(r[1]), "=r"(r[2]), "=r"(r[3]) : "r"(s));
}
__device__ __forceinline__ void mma16816(float* d, const unsigned* a, unsigned b0, unsigned b1) {
    asm volatile("mma.sync.aligned.m16n8k16.row.col.f32.bf16.bf16.f32 "
                 "{%0,%1,%2,%3}, {%4,%5,%6,%7}, {%8,%9}, {%0,%1,%2,%3};"
                 : "+f"(d[0]), "+f"(d[1]), "+f"(d[2]), "+f"(d[3])
                 : "r"(a[0]), "r"(a[1]), "r"(a[2]), "r"(a[3]), "r"(b0), "r"(b1));
}

// ---------------- weight conversion: fp32 [R,K] -> bf16 [R,3K] as (hi, lo, hi) -------------
__global__ __launch_bounds__(256) void wconv_kernel(const float* __restrict__ src,
                                                    __nv_bfloat16* __restrict__ dst,
                                                    int R, int K) {
    long long idx = (long long)blockIdx.x * 256 + threadIdx.x;
    if (idx >= (long long)R * K) return;
    int k = (int)(idx % K);
    long long r = idx / K;
    float w = src[idx];
    __nv_bfloat16 hi, lo;
    split_bf(w, hi, lo);
    size_t b = (size_t)r * 3 * K;
    dst[b + k]         = hi;
    dst[b + K + k]     = lo;
    dst[b + 2 * K + k] = hi;
}

// ---------------- fused QKV weight conversion (scale folded into q rows) ----------------
__global__ __launch_bounds__(256) void wconv_qkv_kernel(const float* __restrict__ qw,
                                                        const float* __restrict__ kw,
                                                        const float* __restrict__ vw,
                                                        __nv_bfloat16* __restrict__ dst) {
    long long idx = (long long)blockIdx.x * 256 + threadIdx.x;
    if (idx >= (long long)Lnum * NQKV * Dm) return;
    int k = (int)(idx % Dm);
    long long rowall = idx / Dm;
    int rr = (int)(rowall % NQKV);
    int l  = (int)(rowall / NQKV);
    float w;
    if (rr < 768)        w = qw[((size_t)l * Dm + rr) * Dm + k] * 0.125f;
    else if (rr < 1536)  w = kw[((size_t)l * Dm + (rr - 768)) * Dm + k];
    else                 w = vw[((size_t)l * Dm + (rr - 1536)) * Dm + k];
    __nv_bfloat16 hi, lo;
    split_bf(w, hi, lo);
    size_t b = (size_t)rowall * K768E;
    dst[b + k]            = hi;
    dst[b + Dm + k]       = lo;
    dst[b + 2 * Dm + k]   = hi;
}

__global__ __launch_bounds__(256) void bconv_qkv_kernel(const float* __restrict__ qb,
                                                        const float* __restrict__ kb,
                                                        const float* __restrict__ vb,
                                                        float* __restrict__ out) {
    int idx = blockIdx.x * 256 + threadIdx.x;
    if (idx >= Lnum * NQKV) return;
    int rr = idx % NQKV, l = idx / NQKV;
    float v;
    if (rr < 768)       v = qb[l * Dm + rr] * 0.125f;
    else if (rr < 1536) v = kb[l * Dm + (rr - 768)];
    else                v = vb[l * Dm + (rr - 1536)];
    out[idx] = v;
}

// ---------------- im2col + expand: image -> ae1 [MPATCH, 2304] as (hi, hi, lo) -------------
__global__ __launch_bounds__(256) void im2col_exp_kernel(const float* __restrict__ img,
                                                         __nv_bfloat16* __restrict__ out) {
    int idx = blockIdx.x * 256 + threadIdx.x;
    if (idx >= MPATCH * Dm) return;
    int k = idx % Dm;
    int m = idx / Dm;
    int b = m / NPATCH, p = m % NPATCH;
    int py = p / 14, px = p % 14;
    int c = k >> 8, i = (k >> 4) & 15, j = k & 15;
    float v = img[(((size_t)b * 3 + c) * 224 + (py * 16 + i)) * 224 + (px * 16 + j)];
    __nv_bfloat16 hi, lo;
    split_bf(v, hi, lo);
    size_t base = (size_t)m * K768E;
    out[base + k]          = hi;
    out[base + Dm + k]     = hi;
    out[base + 2 * Dm + k] = lo;
}

// ---------------- assemble / replace ----------------
__global__ __launch_bounds__(256) void assemble_kernel(const float* __restrict__ feat,
                                                       const float* __restrict__ cls,
                                                       const float* __restrict__ pos,
                                                       const float* __restrict__ gp,
                                                       float* __restrict__ x) {
    int idx = blockIdx.x * blockDim.x + threadIdx.x;
    if (idx >= MTOK * Dm) return;
    int d = idx % Dm;
    int s = (idx / Dm) % STOK;
    int b = idx / (Dm * STOK);
    float v;
    if (s == 0)       v = cls[d] + pos[d];
    else if (s < 197) v = feat[((size_t)(b * NPATCH + s - 1)) * Dm + d] + pos[(size_t)s * Dm + d];
    else              v = gp[(((size_t)b * Lnum + 0) * NPRn + (s - 197)) * Dm + d];
    x[idx] = v;
}

__global__ __launch_bounds__(256) void replace_kernel(float* __restrict__ x,
                                                      const float* __restrict__ gp,
                                                      int layer) {
    int idx = blockIdx.x * blockDim.x + threadIdx.x;
    if (idx >= Bsz * NPRn * Dm) return;
    int d = idx % Dm;
    int r = (idx / Dm) % NPRn;
    int b = idx / (Dm * NPRn);
    x[((size_t)(b * STOK + 197 + r)) * Dm + d] =
        gp[(((size_t)b * Lnum + layer) * NPRn + r) * Dm + d];
}

// ---------------- LayerNorm ----------------
template <int EXPOUT>
__global__ __launch_bounds__(256) void ln_kernel(const float* __restrict__ x,
                                                 const float* __restrict__ g,
                                                 const float* __restrict__ bb,
                                                 void* __restrict__ outp,
                                                 int in_stride, int out_stride) {
    const float* xr = x + (size_t)blockIdx.x * in_stride;
    int t = threadIdx.x;
    float v0 = xr[t], v1 = xr[t + 256], v2 = xr[t + 512];
    float s = v0 + v1 + v2;
    float q = v0 * v0 + v1 * v1 + v2 * v2;
#pragma unroll
    for (int off = 16; off; off >>= 1) {
        s += __shfl_xor_sync(0xffffffffu, s, off);
        q += __shfl_xor_sync(0xffffffffu, q, off);
    }
    __shared__ float ws[8], wq[8], stat[2];
    int w = t >> 5, lane = t & 31;
    if (lane == 0) { ws[w] = s; wq[w] = q; }
    __syncthreads();
    if (t < 32) {
        float s2 = (t < 8) ? ws[t] : 0.f;
        float q2 = (t < 8) ? wq[t] : 0.f;
#pragma unroll
        for (int off = 4; off; off >>= 1) {
            s2 += __shfl_xor_sync(0xffffffffu, s2, off);
            q2 += __shfl_xor_sync(0xffffffffu, q2, off);
        }
        if (t == 0) {
            float mean = s2 * (1.f / 768.f);
            float var  = q2 * (1.f / 768.f) - mean * mean;
            stat[0] = mean;
            stat[1] = rsqrtf(var + 1e-5f);
        }
    }
    __syncthreads();
    float mean = stat[0], inv = stat[1];
    float y0 = (v0 - mean) * inv * g[t]       + bb[t];
    float y1 = (v1 - mean) * inv * g[t + 256] + bb[t + 256];
    float y2 = (v2 - mean) * inv * g[t + 512] + bb[t + 512];
    if (EXPOUT) {
        __nv_bfloat16* o = (__nv_bfloat16*)outp + (size_t)blockIdx.x * K768E;
        __nv_bfloat16 h0, l0, h1, l1, h2, l2;
        split_bf(y0, h0, l0); split_bf(y1, h1, l1); split_bf(y2, h2, l2);
        o[t]        = h0; o[768 + t]        = h0; o[1536 + t]        = l0;
        o[t + 256]  = h1; o[768 + t + 256]  = h1; o[1536 + t + 256]  = l1;
        o[t + 512]  = h2; o[768 + t + 512]  = h2; o[1536 + t + 512]  = l2;
    } else {
        float* o = (float*)outp + (size_t)blockIdx.x * out_stride;
        o[t] = y0; o[t + 256] = y1; o[t + 512] = y2;
    }
}

// ======== persistent bf16 HMMA GEMM, 64x64 warp tiles: C[M,N] = A[M,Kp] @ W[N,Kp]^T ========
// BM=128, BN=256, 8 warps (2x4), 3-stage cp.async. K-tile 32.
// MODE 0: +bias fp32 out; 2: +bias+res fp32 out; 3: quick_gelu(+bias) -> expanded bf16
#define BKt 32
#define SKS 40   // padded K stride in bf16 (80B rows)
#define PGRID 148
#define AST (128*SKS)
#define BST (256*SKS)
#define GSM (3*(AST+BST)*2)    // 92160 bytes

template <int MODE>
__global__ __launch_bounds__(256, 1)
void bgemm_kernel(const __nv_bfloat16* __restrict__ A, const __nv_bfloat16* __restrict__ W,
                  const float* __restrict__ bias, const float* __restrict__ res,
                  void* __restrict__ Cout, int Kp, int N, int Mreal, int resStride, int Mpad) {
    extern __shared__ __nv_bfloat16 smem[];
    __nv_bfloat16* sAb = smem;                 // 3 * AST
    __nv_bfloat16* sBb = smem + 3 * AST;       // 3 * BST

    int tid = threadIdx.x, lane = tid & 31, warp = tid >> 5;
    int wm = (warp >> 2) * 64;                 // 2 M-bands
    int wn = (warp & 3) * 64;                  // 4 N-bands
    int lrow = tid >> 2, lko = (tid & 3) << 3;

    int gx = N >> 8;                           // N / 256
    int ntile = gx * (Mpad >> 7);
    int nk = Kp / BKt;

    for (int tile = blockIdx.x; tile < ntile; tile += gridDim.x) {
        int m0 = (tile / gx) << 7;
        int n0 = (tile % gx) << 8;

        float acc[4][8][4];
#pragma unroll
        for (int i = 0; i < 4; i++)
#pragma unroll
            for (int j = 0; j < 8; j++)
#pragma unroll
                for (int e = 0; e < 4; e++) acc[i][j][e] = 0.f;

        auto load_stage = [&](int st, int k0) {
            __nv_bfloat16* a = sAb + st * AST;
            __nv_bfloat16* b = sBb + st * BST;
            // A: 128 rows x 4 chunks = 512 cp16 (2 per thread)
            cp16(a + lrow * SKS + lko,        A + (size_t)(m0 + lrow) * Kp + k0 + lko);
            cp16(a + (lrow + 64) * SKS + lko, A + (size_t)(m0 + lrow + 64) * Kp + k0 + lko);
            // B: 256 rows x 4 chunks = 1024 cp16 (4 per thread)
#pragma unroll
            for (int jb = 0; jb < 4; jb++)
                cp16(b + (lrow + jb * 64) * SKS + lko,
                     W + (size_t)(n0 + lrow + jb * 64) * Kp + k0 + lko);
            asm volatile("cp.async.commit_group;\n" ::: "memory");
        };

        load_stage(0, 0);
        load_stage(1, BKt);

        int cs = 0, ls = 2;
        for (int t = 0; t < nk; t++) {
            if (t + 1 < nk) asm volatile("cp.async.wait_group 1;\n" ::: "memory");
            else            asm volatile("cp.async.wait_group 0;\n" ::: "memory");
            __syncthreads();
            if (t + 2 < nk) load_stage(ls, (t + 2) * BKt);
            ls = (ls == 2) ? 0 : ls + 1;

            const __nv_bfloat16* as = sAb + cs * AST;
            const __nv_bfloat16* bs = sBb + cs * BST;
            cs = (cs == 2) ? 0 : cs + 1;
#pragma unroll
            for (int kk = 0; kk < 2; kk++) {
                int kof = kk * 16 + ((lane >> 4) << 3);
                int rrow = lane & 15;
                unsigned ar[4][4];
#pragma unroll
                for (int mi = 0; mi < 4; mi++)
                    ldm4(ar[mi], &as[(wm + mi * 16 + rrow) * SKS + kof]);
                unsigned br[4][4];
#pragma unroll
                for (int p = 0; p < 4; p++)
                    ldm4(br[p], &bs[(wn + p * 16 + rrow) * SKS + kof]);
#pragma unroll
                for (int mi = 0; mi < 4; mi++)
#pragma unroll
                    for (int nj = 0; nj < 8; nj++)
                        mma16816(acc[mi][nj], ar[mi],
                                 br[nj >> 1][nj & 1], br[nj >> 1][(nj & 1) + 2]);
            }
        }

        // epilogue (registers -> global)
        int group = lane >> 2, tig = lane & 3;
#pragma unroll
        for (int mi = 0; mi < 4; mi++) {
#pragma unroll
            for (int nj = 0; nj < 8; nj++) {
                int col = n0 + wn + nj * 8 + tig * 2;
                float bx = 0.f, by = 0.f;
                if (bias) { bx = bias[col]; by = bias[col + 1]; }
#pragma unroll
                for (int h = 0; h < 2; h++) {
                    int row = m0 + wm + mi * 16 + group + h * 8;
                    if (row >= Mreal) continue;
                    float c0 = acc[mi][nj][h * 2 + 0] + bx;
                    float c1 = acc[mi][nj][h * 2 + 1] + by;
                    if (MODE == 2) {
                        float2 rr = *(const float2*)(res + (size_t)row * resStride + col);
                        c0 += rr.x; c1 += rr.y;
                    }
                    if (MODE == 3) {
                        c0 = qgelu(c0); c1 = qgelu(c1);
                        __nv_bfloat16 h0, l0, h1, l1;
                        split_bf(c0, h0, l0); split_bf(c1, h1, l1);
                        __nv_bfloat16* Cb = (__nv_bfloat16*)Cout;
                        size_t base = (size_t)row * (3 * N) + col;
                        __nv_bfloat162 hp; hp.x = h0; hp.y = h1;
                        __nv_bfloat162 lp; lp.x = l0; lp.y = l1;
                        *(__nv_bfloat162*)(Cb + base)         = hp;
                        *(__nv_bfloat162*)(Cb + base + N)     = hp;
                        *(__nv_bfloat162*)(Cb + base + 2 * N) = lp;
                    } else {
                        *(float2*)((float*)Cout + (size_t)row * N + col) = make_float2(c0, c1);
                    }
                }
            }
        }
        __syncthreads();   // protect smem stages from next tile's preload
    }
}

// ---------------- fused attention: one block per (b,h); packed qkv input ----------------
#define ATTN_SMEM_FLOATS (2*STOK*65 + 8*64 + 8*208)
__global__ __launch_bounds__(256)
void attn_kernel(const float* __restrict__ qkv, __nv_bfloat16* __restrict__ o) {
    extern __shared__ float sm[];
    float* sK = sm;
    float* sV = sm + STOK * 65;
    float* sQ = sm + 2 * STOK * 65;
    float* sP = sQ + 8 * 64;
    int bh = blockIdx.x;
    int b = bh / Hn, hh = bh % Hn;
    int tid = threadIdx.x;
    size_t base = (size_t)b * STOK * NQKV + (size_t)hh * DHd;

    for (int idx = tid; idx < STOK * DHd; idx += 256) {
        int j = idx >> 6, d = idx & 63;
        size_t gg = base + (size_t)j * NQKV + d;
        sK[j * 65 + d] = qkv[gg + 768];
        sV[j * 65 + d] = qkv[gg + 1536];
    }
    __syncthreads();

    int warp = tid >> 5, lane = tid & 31;
    for (int i = warp; i < STOK; i += 8) {
        const float* qr = qkv + base + (size_t)i * NQKV;
        sQ[warp * 64 + lane]      = qr[lane];
        sQ[warp * 64 + lane + 32] = qr[lane + 32];
        __syncwarp();

        float e[7];
        float mx = -1e30f;
#pragma unroll
        for (int jj = 0; jj < 7; jj++) {
            int j = lane + jj * 32;
            float s = -1e30f;
            if (j < STOK) {
                s = 0.f;
#pragma unroll
                for (int d = 0; d < DHd; d++)
                    s += sQ[warp * 64 + d] * sK[j * 65 + d];
            }
            e[jj] = s;
            mx = fmaxf(mx, s);
        }
#pragma unroll
        for (int off = 16; off; off >>= 1)
            mx = fmaxf(mx, __shfl_xor_sync(0xffffffffu, mx, off));

        float sum = 0.f;
#pragma unroll
        for (int jj = 0; jj < 7; jj++) {
            int j = lane + jj * 32;
            float ev = (j < STOK) ? expf(e[jj] - mx) : 0.f;
            e[jj] = ev;
            sum += ev;
        }
#pragma unroll
        for (int off = 16; off; off >>= 1)
            sum += __shfl_xor_sync(0xffffffffu, sum, off);
        float inv = 1.f / sum;

#pragma unroll
        for (int jj = 0; jj < 7; jj++) {
            int j = lane + jj * 32;
            if (j < STOK) sP[warp * 208 + j] = e[jj] * inv;
        }
        __syncwarp();

        float o0 = 0.f, o1 = 0.f;
        const float* pw = sP + warp * 208;
#pragma unroll 5
        for (int j = 0; j < STOK; j++) {
            float w = pw[j];
            o0 += w * sV[j * 65 + lane];
            o1 += w * sV[j * 65 + lane + 32];
        }
        size_t orow = ((size_t)(b * STOK + i)) * K768E + hh * DHd;
        __nv_bfloat16 h0, l0, h1, l1;
        split_bf(o0, h0, l0); split_bf(o1, h1, l1);
        o[orow + lane]              = h0;
        o[orow + 768 + lane]        = h0;
        o[orow + 1536 + lane]       = l0;
        o[orow + lane + 32]         = h1;
        o[orow + 768 + lane + 32]   = h1;
        o[orow + 1536 + lane + 32]  = l1;
        __syncwarp();
    }
}

// ---------------- host orchestration ----------------
extern "C" void kernel_launch(void* const* d_in, const int* in_sizes, int n_in,
                              void* d_out, int out_size) {
    const float* image   = (const float*)d_in[0];
    const float* gprompt = (const float*)d_in[1];
    const float* patch_w = (const float*)d_in[2];
    const float* cls_emb = (const float*)d_in[3];
    const float* pos_emb = (const float*)d_in[4];
    const float* pre_g   = (const float*)d_in[5];
    const float* pre_b   = (const float*)d_in[6];
    const float* ln1_g   = (const float*)d_in[7];
    const float* ln1_b   = (const float*)d_in[8];
    const float* qw      = (const float*)d_in[9];
    const float* qb      = (const float*)d_in[10];
    const float* kw      = (const float*)d_in[11];
    const float* kb      = (const float*)d_in[12];
    const float* vw      = (const float*)d_in[13];
    const float* vb      = (const float*)d_in[14];
    const float* ow      = (const float*)d_in[15];
    const float* ob      = (const float*)d_in[16];
    const float* ln2_g   = (const float*)d_in[17];
    const float* ln2_b   = (const float*)d_in[18];
    const float* fc1_w   = (const float*)d_in[19];
    const float* fc1_b   = (const float*)d_in[20];
    const float* fc2_w   = (const float*)d_in[21];
    const float* fc2_b   = (const float*)d_in[22];
    const float* post_g  = (const float*)d_in[23];
    const float* post_b  = (const float*)d_in[24];
    float* out = (float*)d_out;

    float *x, *qkv, *bqkv;
    __nv_bfloat16 *ae1, *ae2, *wqkvd, *wod, *w1d, *w2d, *wpd;
    cudaGetSymbolAddress((void**)&x,    g_x);
    cudaGetSymbolAddress((void**)&qkv,  g_qkv);
    cudaGetSymbolAddress((void**)&bqkv, g_bqkv);
    cudaGetSymbolAddress((void**)&ae1,  g_ae1);
    cudaGetSymbolAddress((void**)&ae2,  g_ae2);
    cudaGetSymbolAddress((void**)&wqkvd, g_wqkv);
    cudaGetSymbolAddress((void**)&wod,  g_wo);
    cudaGetSymbolAddress((void**)&w1d,  g_w1);
    cudaGetSymbolAddress((void**)&w2d,  g_w2);
    cudaGetSymbolAddress((void**)&wpd,  g_wp);

    const int attn_smem = ATTN_SMEM_FLOATS * (int)sizeof(float);
    cudaFuncSetAttribute(attn_kernel, cudaFuncAttributeMaxDynamicSharedMemorySize, attn_smem);
    cudaFuncSetAttribute(bgemm_kernel<0>, cudaFuncAttributeMaxDynamicSharedMemorySize, GSM);
    cudaFuncSetAttribute(bgemm_kernel<2>, cudaFuncAttributeMaxDynamicSharedMemorySize, GSM);
    cudaFuncSetAttribute(bgemm_kernel<3>, cudaFuncAttributeMaxDynamicSharedMemorySize, GSM);

    // --- preamble; position #4 (1-based) = conv GEMM for ncu capture ---
    {
        long long n;
        n = (long long)Dm * Dm;                                            // 1
        wconv_kernel<<<(unsigned)((n + 255) / 256), 256>>>(patch_w, wpd, Dm, Dm);
        im2col_exp_kernel<<<(MPATCH * Dm + 255) / 256, 256>>>(image, ae1);  // 2
        bconv_qkv_kernel<<<(Lnum * NQKV + 255) / 256, 256>>>(qb, kb, vb, bqkv); // 3
        // 4: conv GEMM  <- ncu capture target
        bgemm_kernel<0><<<PGRID, 256, GSM>>>(
            ae1, wpd, nullptr, nullptr, qkv, K768E, Dm, MPATCH, 0, MPATCH);
        n = (long long)Lnum * NQKV * Dm;                                    // 5
        wconv_qkv_kernel<<<(unsigned)((n + 255) / 256), 256>>>(qw, kw, vw, wqkvd);
        assemble_kernel<<<(MTOK * Dm + 255) / 256, 256>>>(qkv, cls_emb, pos_emb, gprompt, x); // 6
        ln_kernel<0><<<MTOK, 256>>>(x, pre_g, pre_b, x, Dm, Dm);            // 7
        n = (long long)Lnum * Dm * Dm;                                      // 8
        wconv_kernel<<<(unsigned)((n + 255) / 256), 256>>>(ow, wod, Lnum * Dm, Dm);
        n = (long long)Lnum * FFd * Dm;                                     // 9
        wconv_kernel<<<(unsigned)((n + 255) / 256), 256>>>(fc1_w, w1d, Lnum * FFd, Dm);
        n = (long long)Lnum * Dm * FFd;                                     // 10
        wconv_kernel<<<(unsigned)((n + 255) / 256), 256>>>(fc2_w, w2d, Lnum * Dm, FFd);
    }

    for (int l = 0; l < Lnum; l++) {
        if (l > 0) {
            int tot = Bsz * NPRn * Dm;
            replace_kernel<<<(tot + 255) / 256, 256>>>(x, gprompt, l);
        }
        // attention
        ln_kernel<1><<<MTOK, 256>>>(x, ln1_g + (size_t)l * Dm, ln1_b + (size_t)l * Dm, ae1, Dm, 0);
        bgemm_kernel<0><<<PGRID, 256, GSM>>>(
            ae1, wqkvd + (size_t)l * NQKV * K768E, bqkv + (size_t)l * NQKV,
            nullptr, qkv, K768E, NQKV, MTOK, 0, MPAD);
        attn_kernel<<<Bsz * Hn, 256, attn_smem>>>(qkv, ae1);
        bgemm_kernel<2><<<PGRID, 256, GSM>>>(
            ae1, wod + (size_t)l * Dm * K768E, ob + (size_t)l * Dm,
            x, x, K768E, Dm, MTOK, Dm, MPAD);
        // MLP
        ln_kernel<1><<<MTOK, 256>>>(x, ln2_g + (size_t)l * Dm, ln2_b + (size_t)l * Dm, ae1, Dm, 0);
        bgemm_kernel<3><<<PGRID, 256, GSM>>>(
            ae1, w1d + (size_t)l * FFd * K768E, fc1_b + (size_t)l * FFd,
            nullptr, ae2, K768E, FFd, MTOK, 0, MPAD);
        bgemm_kernel<2><<<PGRID, 256, GSM>>>(
            ae2, w2d + (size_t)l * Dm * KFFE, fc2_b + (size_t)l * Dm,
            x, x, KFFE, Dm, MTOK, Dm, MPAD);
    }

    ln_kernel<0><<<Bsz, 256>>>(x, post_g, post_b, out, STOK * Dm, Dm);
}

// round 10
// speedup vs baseline: 2.0459x; 2.0459x over previous
#include <cuda_runtime.h>
#include <cuda_fp16.h>
#include <math.h>
#include <stdint.h>

// ---------------- problem constants ----------------
#define Bsz    64
#define Dm     768
#define Hn     12
#define DHd    64
#define Lnum   12
#define FFd    3072
#define NPRn   8
#define STOK   205
#define NPATCH 196
#define MTOK   (Bsz*STOK)     // 13120
#define MPATCH (Bsz*NPATCH)   // 12544 = 98*128
#define MPAD   13184          // 103*128 >= MTOK
#define NQKV   2304           // fused q|k|v output width

// ---------------- static device scratch ----------------
__device__ float g_x[MPAD*Dm];
__device__ float g_qkv[(size_t)MPAD*NQKV];        // packed q|k|v fp32
__device__ float  g_bqkv[(size_t)Lnum*NQKV];
__device__ __half g_ae1[(size_t)MPAD*Dm];         // fp16 activations (K=768 GEMMs)
__device__ __half g_ae2[(size_t)MPAD*FFd];        // fp16 MLP hidden
__device__ __half g_wqkv[(size_t)Lnum*NQKV*Dm];
__device__ __half g_wo[(size_t)Lnum*Dm*Dm];
__device__ __half g_w1[(size_t)Lnum*FFd*Dm];
__device__ __half g_w2[(size_t)Lnum*Dm*FFd];
__device__ __half g_wp[(size_t)Dm*Dm];

// ---------------- helpers ----------------
__device__ __forceinline__ float qgelu(float x) {
    return x / (1.f + expf(-1.702f * x));
}
__device__ __forceinline__ void cp16(void* s, const void* g) {
    unsigned sa = (unsigned)__cvta_generic_to_shared(s);
    asm volatile("cp.async.ca.shared.global [%0], [%1], 16;\n" :: "r"(sa), "l"(g));
}
__device__ __forceinline__ void ldm4(unsigned* r, const __half* p) {
    unsigned s = (unsigned)__cvta_generic_to_shared(p);
    asm volatile("ldmatrix.sync.aligned.m8n8.x4.shared.b16 {%0,%1,%2,%3}, [%4];"
                 : "=r"(r[0]), "=r"(r[1]), "=r"(r[2]), "=r"(r[3]) : "r"(s));
}
__device__ __forceinline__ void mma16816(float* d, const unsigned* a, unsigned b0, unsigned b1) {
    asm volatile("mma.sync.aligned.m16n8k16.row.col.f32.f16.f16.f32 "
                 "{%0,%1,%2,%3}, {%4,%5,%6,%7}, {%8,%9}, {%0,%1,%2,%3};"
                 : "+f"(d[0]), "+f"(d[1]), "+f"(d[2]), "+f"(d[3])
                 : "r"(a[0]), "r"(a[1]), "r"(a[2]), "r"(a[3]), "r"(b0), "r"(b1));
}

// ---------------- weight conversion: fp32 -> fp16, same layout ----------------
__global__ __launch_bounds__(256) void wconv_kernel(const float* __restrict__ src,
                                                    __half* __restrict__ dst,
                                                    long long total) {
    long long idx = (long long)blockIdx.x * 256 + threadIdx.x;
    if (idx >= total) return;
    dst[idx] = __float2half(src[idx]);
}

// ---------------- fused QKV weight conversion (scale folded into q rows) ----------------
__global__ __launch_bounds__(256) void wconv_qkv_kernel(const float* __restrict__ qw,
                                                        const float* __restrict__ kw,
                                                        const float* __restrict__ vw,
                                                        __half* __restrict__ dst) {
    long long idx = (long long)blockIdx.x * 256 + threadIdx.x;
    if (idx >= (long long)Lnum * NQKV * Dm) return;
    int k = (int)(idx % Dm);
    long long rowall = idx / Dm;
    int rr = (int)(rowall % NQKV);
    int l  = (int)(rowall / NQKV);
    float w;
    if (rr < 768)        w = qw[((size_t)l * Dm + rr) * Dm + k] * 0.125f;
    else if (rr < 1536)  w = kw[((size_t)l * Dm + (rr - 768)) * Dm + k];
    else                 w = vw[((size_t)l * Dm + (rr - 1536)) * Dm + k];
    dst[idx] = __float2half(w);
}

__global__ __launch_bounds__(256) void bconv_qkv_kernel(const float* __restrict__ qb,
                                                        const float* __restrict__ kb,
                                                        const float* __restrict__ vb,
                                                        float* __restrict__ out) {
    int idx = blockIdx.x * 256 + threadIdx.x;
    if (idx >= Lnum * NQKV) return;
    int rr = idx % NQKV, l = idx / NQKV;
    float v;
    if (rr < 768)       v = qb[l * Dm + rr] * 0.125f;
    else if (rr < 1536) v = kb[l * Dm + (rr - 768)];
    else                v = vb[l * Dm + (rr - 1536)];
    out[idx] = v;
}

// ---------------- im2col fp16: image -> ae1 [MPATCH, 768] ----------------
__global__ __launch_bounds__(256) void im2col_kernel(const float* __restrict__ img,
                                                     __half* __restrict__ out) {
    int idx = blockIdx.x * 256 + threadIdx.x;
    if (idx >= MPATCH * Dm) return;
    int k = idx % Dm;
    int m = idx / Dm;
    int b = m / NPATCH, p = m % NPATCH;
    int py = p / 14, px = p % 14;
    int c = k >> 8, i = (k >> 4) & 15, j = k & 15;
    out[idx] = __float2half(
        img[(((size_t)b * 3 + c) * 224 + (py * 16 + i)) * 224 + (px * 16 + j)]);
}

// ---------------- assemble / replace ----------------
__global__ __launch_bounds__(256) void assemble_kernel(const float* __restrict__ feat,
                                                       const float* __restrict__ cls,
                                                       const float* __restrict__ pos,
                                                       const float* __restrict__ gp,
                                                       float* __restrict__ x) {
    int idx = blockIdx.x * blockDim.x + threadIdx.x;
    if (idx >= MTOK * Dm) return;
    int d = idx % Dm;
    int s = (idx / Dm) % STOK;
    int b = idx / (Dm * STOK);
    float v;
    if (s == 0)       v = cls[d] + pos[d];
    else if (s < 197) v = feat[((size_t)(b * NPATCH + s - 1)) * Dm + d] + pos[(size_t)s * Dm + d];
    else              v = gp[(((size_t)b * Lnum + 0) * NPRn + (s - 197)) * Dm + d];
    x[idx] = v;
}

__global__ __launch_bounds__(256) void replace_kernel(float* __restrict__ x,
                                                      const float* __restrict__ gp,
                                                      int layer) {
    int idx = blockIdx.x * blockDim.x + threadIdx.x;
    if (idx >= Bsz * NPRn * Dm) return;
    int d = idx % Dm;
    int r = (idx / Dm) % NPRn;
    int b = idx / (Dm * NPRn);
    x[((size_t)(b * STOK + 197 + r)) * Dm + d] =
        gp[(((size_t)b * Lnum + layer) * NPRn + r) * Dm + d];
}

// ---------------- LayerNorm: EXPOUT=0 fp32 out, EXPOUT=1 fp16 out (stride 768) ----------
template <int EXPOUT>
__global__ __launch_bounds__(256) void ln_kernel(const float* __restrict__ x,
                                                 const float* __restrict__ g,
                                                 const float* __restrict__ bb,
                                                 void* __restrict__ outp,
                                                 int in_stride, int out_stride) {
    const float* xr = x + (size_t)blockIdx.x * in_stride;
    int t = threadIdx.x;
    float v0 = xr[t], v1 = xr[t + 256], v2 = xr[t + 512];
    float s = v0 + v1 + v2;
    float q = v0 * v0 + v1 * v1 + v2 * v2;
#pragma unroll
    for (int off = 16; off; off >>= 1) {
        s += __shfl_xor_sync(0xffffffffu, s, off);
        q += __shfl_xor_sync(0xffffffffu, q, off);
    }
    __shared__ float ws[8], wq[8], stat[2];
    int w = t >> 5, lane = t & 31;
    if (lane == 0) { ws[w] = s; wq[w] = q; }
    __syncthreads();
    if (t < 32) {
        float s2 = (t < 8) ? ws[t] : 0.f;
        float q2 = (t < 8) ? wq[t] : 0.f;
#pragma unroll
        for (int off = 4; off; off >>= 1) {
            s2 += __shfl_xor_sync(0xffffffffu, s2, off);
            q2 += __shfl_xor_sync(0xffffffffu, q2, off);
        }
        if (t == 0) {
            float mean = s2 * (1.f / 768.f);
            float var  = q2 * (1.f / 768.f) - mean * mean;
            stat[0] = mean;
            stat[1] = rsqrtf(var + 1e-5f);
        }
    }
    __syncthreads();
    float mean = stat[0], inv = stat[1];
    float y0 = (v0 - mean) * inv * g[t]       + bb[t];
    float y1 = (v1 - mean) * inv * g[t + 256] + bb[t + 256];
    float y2 = (v2 - mean) * inv * g[t + 512] + bb[t + 512];
    if (EXPOUT) {
        __half* o = (__half*)outp + (size_t)blockIdx.x * Dm;
        o[t]       = __float2half(y0);
        o[t + 256] = __float2half(y1);
        o[t + 512] = __float2half(y2);
    } else {
        float* o = (float*)outp + (size_t)blockIdx.x * out_stride;
        o[t] = y0; o[t + 256] = y1; o[t + 512] = y2;
    }
}

// ======== fp16 HMMA GEMM (R5-proven config): C[M,N] = A[M,Kp] @ W[N,Kp]^T ========
// BM=128, BN=128, warp 64x32, 256 thr, 2 CTA/SM, 3-stage cp.async, K-tile 32.
// MODE 0: +bias fp32 out; 2: +bias+res fp32 out; 3: quick_gelu(+bias) -> fp16 out
#define BKt 32
#define SKS 40   // padded K stride in fp16 (80B rows)
#define STG (128*SKS)
#define GSM (6*STG*2)    // 3 stages x (A+B) x 128 rows x 40 x 2B = 61440

template <int MODE>
__global__ __launch_bounds__(256, 2)
void bgemm_kernel(const __half* __restrict__ A, const __half* __restrict__ W,
                  const float* __restrict__ bias, const float* __restrict__ res,
                  void* __restrict__ Cout, int Kp, int N, int Mreal, int resStride) {
    extern __shared__ __half smem[];
    __half* sAb = smem;             // 3 * STG
    __half* sBb = smem + 3 * STG;   // 3 * STG

    int tid = threadIdx.x, lane = tid & 31, warp = tid >> 5;
    int m0 = blockIdx.y * 128, n0 = blockIdx.x * 128;
    int wm = (warp >> 2) * 64, wn = (warp & 3) * 32;
    int lrow = tid >> 2, lko = (tid & 3) << 3;

    float acc[4][4][4];
#pragma unroll
    for (int i = 0; i < 4; i++)
#pragma unroll
        for (int j = 0; j < 4; j++)
#pragma unroll
            for (int e = 0; e < 4; e++) acc[i][j][e] = 0.f;

    auto load_stage = [&](int st, int k0) {
        __half* a = sAb + st * STG;
        __half* b = sBb + st * STG;
        cp16(a + lrow * SKS + lko,        A + (size_t)(m0 + lrow) * Kp + k0 + lko);
        cp16(a + (lrow + 64) * SKS + lko, A + (size_t)(m0 + lrow + 64) * Kp + k0 + lko);
        cp16(b + lrow * SKS + lko,        W + (size_t)(n0 + lrow) * Kp + k0 + lko);
        cp16(b + (lrow + 64) * SKS + lko, W + (size_t)(n0 + lrow + 64) * Kp + k0 + lko);
        asm volatile("cp.async.commit_group;\n" ::: "memory");
    };

    int nk = Kp / BKt;
    load_stage(0, 0);
    load_stage(1, BKt);

    int cs = 0, ls = 2;
    for (int t = 0; t < nk; t++) {
        if (t + 1 < nk) asm volatile("cp.async.wait_group 1;\n" ::: "memory");
        else            asm volatile("cp.async.wait_group 0;\n" ::: "memory");
        __syncthreads();
        if (t + 2 < nk) load_stage(ls, (t + 2) * BKt);
        ls = (ls == 2) ? 0 : ls + 1;

        const __half* as = sAb + cs * STG;
        const __half* bs = sBb + cs * STG;
        cs = (cs == 2) ? 0 : cs + 1;
#pragma unroll
        for (int kk = 0; kk < 2; kk++) {
            int kof = kk * 16 + ((lane >> 4) << 3);
            int rrow = lane & 15;
            unsigned ar[4][4];
#pragma unroll
            for (int mi = 0; mi < 4; mi++)
                ldm4(ar[mi], &as[(wm + mi * 16 + rrow) * SKS + kof]);
            unsigned br[2][4];
#pragma unroll
            for (int p = 0; p < 2; p++)
                ldm4(br[p], &bs[(wn + p * 16 + rrow) * SKS + kof]);
#pragma unroll
            for (int mi = 0; mi < 4; mi++)
#pragma unroll
                for (int nj = 0; nj < 4; nj++)
                    mma16816(acc[mi][nj], ar[mi], br[nj >> 1][nj & 1], br[nj >> 1][(nj & 1) + 2]);
        }
        // single top barrier per iter protects stage reuse
    }

    // epilogue (registers -> global)
    int group = lane >> 2, tig = lane & 3;
#pragma unroll
    for (int mi = 0; mi < 4; mi++) {
#pragma unroll
        for (int nj = 0; nj < 4; nj++) {
            int col = n0 + wn + nj * 8 + tig * 2;
            float bx = 0.f, by = 0.f;
            if (bias) { bx = bias[col]; by = bias[col + 1]; }
#pragma unroll
            for (int h = 0; h < 2; h++) {
                int row = m0 + wm + mi * 16 + group + h * 8;
                if (row >= Mreal) continue;
                float c0 = acc[mi][nj][h * 2 + 0] + bx;
                float c1 = acc[mi][nj][h * 2 + 1] + by;
                if (MODE == 2) {
                    float2 rr = *(const float2*)(res + (size_t)row * resStride + col);
                    c0 += rr.x; c1 += rr.y;
                }
                if (MODE == 3) {
                    __half2 hp;
                    hp.x = __float2half(qgelu(c0));
                    hp.y = __float2half(qgelu(c1));
                    *(__half2*)((__half*)Cout + (size_t)row * N + col) = hp;
                } else {
                    *(float2*)((float*)Cout + (size_t)row * N + col) = make_float2(c0, c1);
                }
            }
        }
    }
}

// ---------------- fused attention: one block per (b,h); packed qkv input; fp16 out --------
#define ATTN_SMEM_FLOATS (2*STOK*65 + 8*64 + 8*208)
__global__ __launch_bounds__(256)
void attn_kernel(const float* __restrict__ qkv, __half* __restrict__ o) {
    extern __shared__ float sm[];
    float* sK = sm;
    float* sV = sm + STOK * 65;
    float* sQ = sm + 2 * STOK * 65;
    float* sP = sQ + 8 * 64;
    int bh = blockIdx.x;
    int b = bh / Hn, hh = bh % Hn;
    int tid = threadIdx.x;
    size_t base = (size_t)b * STOK * NQKV + (size_t)hh * DHd;

    for (int idx = tid; idx < STOK * DHd; idx += 256) {
        int j = idx >> 6, d = idx & 63;
        size_t gg = base + (size_t)j * NQKV + d;
        sK[j * 65 + d] = qkv[gg + 768];
        sV[j * 65 + d] = qkv[gg + 1536];
    }
    __syncthreads();

    int warp = tid >> 5, lane = tid & 31;
    for (int i = warp; i < STOK; i += 8) {
        const float* qr = qkv + base + (size_t)i * NQKV;
        sQ[warp * 64 + lane]      = qr[lane];
        sQ[warp * 64 + lane + 32] = qr[lane + 32];
        __syncwarp();

        float e[7];
        float mx = -1e30f;
#pragma unroll
        for (int jj = 0; jj < 7; jj++) {
            int j = lane + jj * 32;
            float s = -1e30f;
            if (j < STOK) {
                s = 0.f;
#pragma unroll
                for (int d = 0; d < DHd; d++)
                    s += sQ[warp * 64 + d] * sK[j * 65 + d];
            }
            e[jj] = s;
            mx = fmaxf(mx, s);
        }
#pragma unroll
        for (int off = 16; off; off >>= 1)
            mx = fmaxf(mx, __shfl_xor_sync(0xffffffffu, mx, off));

        float sum = 0.f;
#pragma unroll
        for (int jj = 0; jj < 7; jj++) {
            int j = lane + jj * 32;
            float ev = (j < STOK) ? expf(e[jj] - mx) : 0.f;
            e[jj] = ev;
            sum += ev;
        }
#pragma unroll
        for (int off = 16; off; off >>= 1)
            sum += __shfl_xor_sync(0xffffffffu, sum, off);
        float inv = 1.f / sum;

#pragma unroll
        for (int jj = 0; jj < 7; jj++) {
            int j = lane + jj * 32;
            if (j < STOK) sP[warp * 208 + j] = e[jj] * inv;
        }
        __syncwarp();

        float o0 = 0.f, o1 = 0.f;
        const float* pw = sP + warp * 208;
#pragma unroll 5
        for (int j = 0; j < STOK; j++) {
            float w = pw[j];
            o0 += w * sV[j * 65 + lane];
            o1 += w * sV[j * 65 + lane + 32];
        }
        size_t orow = ((size_t)(b * STOK + i)) * Dm + hh * DHd;
        o[orow + lane]      = __float2half(o0);
        o[orow + lane + 32] = __float2half(o1);
        __syncwarp();
    }
}

// ---------------- host orchestration ----------------
extern "C" void kernel_launch(void* const* d_in, const int* in_sizes, int n_in,
                              void* d_out, int out_size) {
    const float* image   = (const float*)d_in[0];
    const float* gprompt = (const float*)d_in[1];
    const float* patch_w = (const float*)d_in[2];
    const float* cls_emb = (const float*)d_in[3];
    const float* pos_emb = (const float*)d_in[4];
    const float* pre_g   = (const float*)d_in[5];
    const float* pre_b   = (const float*)d_in[6];
    const float* ln1_g   = (const float*)d_in[7];
    const float* ln1_b   = (const float*)d_in[8];
    const float* qw      = (const float*)d_in[9];
    const float* qb      = (const float*)d_in[10];
    const float* kw      = (const float*)d_in[11];
    const float* kb      = (const float*)d_in[12];
    const float* vw      = (const float*)d_in[13];
    const float* vb      = (const float*)d_in[14];
    const float* ow      = (const float*)d_in[15];
    const float* ob      = (const float*)d_in[16];
    const float* ln2_g   = (const float*)d_in[17];
    const float* ln2_b   = (const float*)d_in[18];
    const float* fc1_w   = (const float*)d_in[19];
    const float* fc1_b   = (const float*)d_in[20];
    const float* fc2_w   = (const float*)d_in[21];
    const float* fc2_b   = (const float*)d_in[22];
    const float* post_g  = (const float*)d_in[23];
    const float* post_b  = (const float*)d_in[24];
    float* out = (float*)d_out;

    float *x, *qkv, *bqkv;
    __half *ae1, *ae2, *wqkvd, *wod, *w1d, *w2d, *wpd;
    cudaGetSymbolAddress((void**)&x,    g_x);
    cudaGetSymbolAddress((void**)&qkv,  g_qkv);
    cudaGetSymbolAddress((void**)&bqkv, g_bqkv);
    cudaGetSymbolAddress((void**)&ae1,  g_ae1);
    cudaGetSymbolAddress((void**)&ae2,  g_ae2);
    cudaGetSymbolAddress((void**)&wqkvd, g_wqkv);
    cudaGetSymbolAddress((void**)&wod,  g_wo);
    cudaGetSymbolAddress((void**)&w1d,  g_w1);
    cudaGetSymbolAddress((void**)&w2d,  g_w2);
    cudaGetSymbolAddress((void**)&wpd,  g_wp);

    const int attn_smem = ATTN_SMEM_FLOATS * (int)sizeof(float);
    cudaFuncSetAttribute(attn_kernel, cudaFuncAttributeMaxDynamicSharedMemorySize, attn_smem);
    cudaFuncSetAttribute(bgemm_kernel<0>, cudaFuncAttributeMaxDynamicSharedMemorySize, GSM);
    cudaFuncSetAttribute(bgemm_kernel<2>, cudaFuncAttributeMaxDynamicSharedMemorySize, GSM);
    cudaFuncSetAttribute(bgemm_kernel<3>, cudaFuncAttributeMaxDynamicSharedMemorySize, GSM);

    // --- preamble; position #4 (1-based) = conv GEMM for ncu capture ---
    {
        long long n;
        n = (long long)Dm * Dm;                                            // 1
        wconv_kernel<<<(unsigned)((n + 255) / 256), 256>>>(patch_w, wpd, n);
        im2col_kernel<<<(MPATCH * Dm + 255) / 256, 256>>>(image, ae1);      // 2
        bconv_qkv_kernel<<<(Lnum * NQKV + 255) / 256, 256>>>(qb, kb, vb, bqkv); // 3
        // 4: conv GEMM  <- ncu capture target
        bgemm_kernel<0><<<dim3(Dm / 128, MPATCH / 128), 256, GSM>>>(
            ae1, wpd, nullptr, nullptr, qkv, Dm, Dm, MPATCH, 0);
        n = (long long)Lnum * NQKV * Dm;                                    // 5
        wconv_qkv_kernel<<<(unsigned)((n + 255) / 256), 256>>>(qw, kw, vw, wqkvd);
        assemble_kernel<<<(MTOK * Dm + 255) / 256, 256>>>(qkv, cls_emb, pos_emb, gprompt, x); // 6
        ln_kernel<0><<<MTOK, 256>>>(x, pre_g, pre_b, x, Dm, Dm);            // 7
        n = (long long)Lnum * Dm * Dm;                                      // 8
        wconv_kernel<<<(unsigned)((n + 255) / 256), 256>>>(ow, wod, n);
        n = (long long)Lnum * FFd * Dm;                                     // 9
        wconv_kernel<<<(unsigned)((n + 255) / 256), 256>>>(fc1_w, w1d, n);
        n = (long long)Lnum * Dm * FFd;                                     // 10
        wconv_kernel<<<(unsigned)((n + 255) / 256), 256>>>(fc2_w, w2d, n);
    }

    dim3 g768(Dm / 128, MPAD / 128);    // (6, 103)
    dim3 gqkv(NQKV / 128, MPAD / 128);  // (18, 103)
    dim3 gff(FFd / 128, MPAD / 128);    // (24, 103)

    for (int l = 0; l < Lnum; l++) {
        if (l > 0) {
            int tot = Bsz * NPRn * Dm;
            replace_kernel<<<(tot + 255) / 256, 256>>>(x, gprompt, l);
        }
        // attention
        ln_kernel<1><<<MTOK, 256>>>(x, ln1_g + (size_t)l * Dm, ln1_b + (size_t)l * Dm, ae1, Dm, 0);
        bgemm_kernel<0><<<gqkv, 256, GSM>>>(
            ae1, wqkvd + (size_t)l * NQKV * Dm, bqkv + (size_t)l * NQKV,
            nullptr, qkv, Dm, NQKV, MTOK, 0);
        attn_kernel<<<Bsz * Hn, 256, attn_smem>>>(qkv, ae1);
        bgemm_kernel<2><<<g768, 256, GSM>>>(
            ae1, wod + (size_t)l * Dm * Dm, ob + (size_t)l * Dm,
            x, x, Dm, Dm, MTOK, Dm);
        // MLP
        ln_kernel<1><<<MTOK, 256>>>(x, ln2_g + (size_t)l * Dm, ln2_b + (size_t)l * Dm, ae1, Dm, 0);
        bgemm_kernel<3><<<gff, 256, GSM>>>(
            ae1, w1d + (size_t)l * FFd * Dm, fc1_b + (size_t)l * FFd,
            nullptr, ae2, Dm, FFd, MTOK, 0);
        bgemm_kernel<2><<<g768, 256, GSM>>>(
            ae2, w2d + (size_t)l * Dm * FFd, fc2_b + (size_t)l * Dm,
            x, x, FFd, Dm, MTOK, Dm);
    }

    ln_kernel<0><<<Bsz, 256>>>(x, post_g, post_b, out, STOK * Dm, Dm);
}

// round 11
// speedup vs baseline: 2.4006x; 1.1734x over previous
#include <cuda_runtime.h>
#include <cuda_fp16.h>
#include <math.h>
#include <stdint.h>

// ---------------- problem constants ----------------
#define Bsz    64
#define Dm     768
#define Hn     12
#define DHd    64
#define Lnum   12
#define FFd    3072
#define NPRn   8
#define STOK   205
#define NPATCH 196
#define MTOK   (Bsz*STOK)     // 13120
#define MPATCH (Bsz*NPATCH)   // 12544 = 98*128
#define MPAD   13184          // 103*128 >= MTOK
#define NQKV   2304           // fused q|k|v output width

// ---------------- static device scratch ----------------
__device__ float g_x[MPAD*Dm];
__device__ float g_qkv[(size_t)MPAD*NQKV];        // packed q|k|v fp32
__device__ float  g_bqkv[(size_t)Lnum*NQKV];
__device__ __half g_ae1[(size_t)MPAD*Dm];         // fp16 activations (K=768 GEMMs)
__device__ __half g_ae2[(size_t)MPAD*FFd];        // fp16 MLP hidden
__device__ __half g_wqkv[(size_t)Lnum*NQKV*Dm];
__device__ __half g_wo[(size_t)Lnum*Dm*Dm];
__device__ __half g_w1[(size_t)Lnum*FFd*Dm];
__device__ __half g_w2[(size_t)Lnum*Dm*FFd];
__device__ __half g_wp[(size_t)Dm*Dm];

// ---------------- helpers ----------------
__device__ __forceinline__ float qgelu(float x) {
    return x / (1.f + expf(-1.702f * x));
}
__device__ __forceinline__ void cp16(void* s, const void* g) {
    unsigned sa = (unsigned)__cvta_generic_to_shared(s);
    asm volatile("cp.async.ca.shared.global [%0], [%1], 16;\n" :: "r"(sa), "l"(g));
}
__device__ __forceinline__ void ldm4(unsigned* r, const __half* p) {
    unsigned s = (unsigned)__cvta_generic_to_shared(p);
    asm volatile("ldmatrix.sync.aligned.m8n8.x4.shared.b16 {%0,%1,%2,%3}, [%4];"
                 : "=r"(r[0]), "=r"(r[1]), "=r"(r[2]), "=r"(r[3]) : "r"(s));
}
__device__ __forceinline__ void mma16816(float* d, const unsigned* a, unsigned b0, unsigned b1) {
    asm volatile("mma.sync.aligned.m16n8k16.row.col.f32.f16.f16.f32 "
                 "{%0,%1,%2,%3}, {%4,%5,%6,%7}, {%8,%9}, {%0,%1,%2,%3};"
                 : "+f"(d[0]), "+f"(d[1]), "+f"(d[2]), "+f"(d[3])
                 : "r"(a[0]), "r"(a[1]), "r"(a[2]), "r"(a[3]), "r"(b0), "r"(b1));
}

// ---------------- weight conversion: fp32 -> fp16, same layout ----------------
__global__ __launch_bounds__(256) void wconv_kernel(const float* __restrict__ src,
                                                    __half* __restrict__ dst,
                                                    long long total) {
    long long idx = (long long)blockIdx.x * 256 + threadIdx.x;
    if (idx >= total) return;
    dst[idx] = __float2half(src[idx]);
}

// ---------------- fused QKV weight conversion (scale folded into q rows) ----------------
__global__ __launch_bounds__(256) void wconv_qkv_kernel(const float* __restrict__ qw,
                                                        const float* __restrict__ kw,
                                                        const float* __restrict__ vw,
                                                        __half* __restrict__ dst) {
    long long idx = (long long)blockIdx.x * 256 + threadIdx.x;
    if (idx >= (long long)Lnum * NQKV * Dm) return;
    int k = (int)(idx % Dm);
    long long rowall = idx / Dm;
    int rr = (int)(rowall % NQKV);
    int l  = (int)(rowall / NQKV);
    float w;
    if (rr < 768)        w = qw[((size_t)l * Dm + rr) * Dm + k] * 0.125f;
    else if (rr < 1536)  w = kw[((size_t)l * Dm + (rr - 768)) * Dm + k];
    else                 w = vw[((size_t)l * Dm + (rr - 1536)) * Dm + k];
    dst[idx] = __float2half(w);
}

__global__ __launch_bounds__(256) void bconv_qkv_kernel(const float* __restrict__ qb,
                                                        const float* __restrict__ kb,
                                                        const float* __restrict__ vb,
                                                        float* __restrict__ out) {
    int idx = blockIdx.x * 256 + threadIdx.x;
    if (idx >= Lnum * NQKV) return;
    int rr = idx % NQKV, l = idx / NQKV;
    float v;
    if (rr < 768)       v = qb[l * Dm + rr] * 0.125f;
    else if (rr < 1536) v = kb[l * Dm + (rr - 768)];
    else                v = vb[l * Dm + (rr - 1536)];
    out[idx] = v;
}

// ---------------- im2col fp16: image -> ae1 [MPATCH, 768] ----------------
__global__ __launch_bounds__(256) void im2col_kernel(const float* __restrict__ img,
                                                     __half* __restrict__ out) {
    int idx = blockIdx.x * 256 + threadIdx.x;
    if (idx >= MPATCH * Dm) return;
    int k = idx % Dm;
    int m = idx / Dm;
    int b = m / NPATCH, p = m % NPATCH;
    int py = p / 14, px = p % 14;
    int c = k >> 8, i = (k >> 4) & 15, j = k & 15;
    out[idx] = __float2half(
        img[(((size_t)b * 3 + c) * 224 + (py * 16 + i)) * 224 + (px * 16 + j)]);
}

// ---------------- assemble / replace ----------------
__global__ __launch_bounds__(256) void assemble_kernel(const float* __restrict__ feat,
                                                       const float* __restrict__ cls,
                                                       const float* __restrict__ pos,
                                                       const float* __restrict__ gp,
                                                       float* __restrict__ x) {
    int idx = blockIdx.x * blockDim.x + threadIdx.x;
    if (idx >= MTOK * Dm) return;
    int d = idx % Dm;
    int s = (idx / Dm) % STOK;
    int b = idx / (Dm * STOK);
    float v;
    if (s == 0)       v = cls[d] + pos[d];
    else if (s < 197) v = feat[((size_t)(b * NPATCH + s - 1)) * Dm + d] + pos[(size_t)s * Dm + d];
    else              v = gp[(((size_t)b * Lnum + 0) * NPRn + (s - 197)) * Dm + d];
    x[idx] = v;
}

__global__ __launch_bounds__(256) void replace_kernel(float* __restrict__ x,
                                                      const float* __restrict__ gp,
                                                      int layer) {
    int idx = blockIdx.x * blockDim.x + threadIdx.x;
    if (idx >= Bsz * NPRn * Dm) return;
    int d = idx % Dm;
    int r = (idx / Dm) % NPRn;
    int b = idx / (Dm * NPRn);
    x[((size_t)(b * STOK + 197 + r)) * Dm + d] =
        gp[(((size_t)b * Lnum + layer) * NPRn + r) * Dm + d];
}

// ---------------- LayerNorm: EXPOUT=0 fp32 out, EXPOUT=1 fp16 out (stride 768) ----------
template <int EXPOUT>
__global__ __launch_bounds__(256) void ln_kernel(const float* __restrict__ x,
                                                 const float* __restrict__ g,
                                                 const float* __restrict__ bb,
                                                 void* __restrict__ outp,
                                                 int in_stride, int out_stride) {
    const float* xr = x + (size_t)blockIdx.x * in_stride;
    int t = threadIdx.x;
    float v0 = xr[t], v1 = xr[t + 256], v2 = xr[t + 512];
    float s = v0 + v1 + v2;
    float q = v0 * v0 + v1 * v1 + v2 * v2;
#pragma unroll
    for (int off = 16; off; off >>= 1) {
        s += __shfl_xor_sync(0xffffffffu, s, off);
        q += __shfl_xor_sync(0xffffffffu, q, off);
    }
    __shared__ float ws[8], wq[8], stat[2];
    int w = t >> 5, lane = t & 31;
    if (lane == 0) { ws[w] = s; wq[w] = q; }
    __syncthreads();
    if (t < 32) {
        float s2 = (t < 8) ? ws[t] : 0.f;
        float q2 = (t < 8) ? wq[t] : 0.f;
#pragma unroll
        for (int off = 4; off; off >>= 1) {
            s2 += __shfl_xor_sync(0xffffffffu, s2, off);
            q2 += __shfl_xor_sync(0xffffffffu, q2, off);
        }
        if (t == 0) {
            float mean = s2 * (1.f / 768.f);
            float var  = q2 * (1.f / 768.f) - mean * mean;
            stat[0] = mean;
            stat[1] = rsqrtf(var + 1e-5f);
        }
    }
    __syncthreads();
    float mean = stat[0], inv = stat[1];
    float y0 = (v0 - mean) * inv * g[t]       + bb[t];
    float y1 = (v1 - mean) * inv * g[t + 256] + bb[t + 256];
    float y2 = (v2 - mean) * inv * g[t + 512] + bb[t + 512];
    if (EXPOUT) {
        __half* o = (__half*)outp + (size_t)blockIdx.x * Dm;
        o[t]       = __float2half(y0);
        o[t + 256] = __float2half(y1);
        o[t + 512] = __float2half(y2);
    } else {
        float* o = (float*)outp + (size_t)blockIdx.x * out_stride;
        o[t] = y0; o[t + 256] = y1; o[t + 512] = y2;
    }
}

// ======== fp16 HMMA GEMM (R5-proven config): C[M,N] = A[M,Kp] @ W[N,Kp]^T ========
// BM=128, BN=128, warp 64x32, 256 thr, 2 CTA/SM, 3-stage cp.async, K-tile 32.
// MODE 0: +bias fp32 out; 2: +bias+res fp32 out; 3: quick_gelu(+bias) -> fp16 out
#define BKt 32
#define SKS 40   // padded K stride in fp16 (80B rows)
#define STG (128*SKS)
#define GSM (6*STG*2)    // 3 stages x (A+B) x 128 rows x 40 x 2B = 61440

template <int MODE>
__global__ __launch_bounds__(256, 2)
void bgemm_kernel(const __half* __restrict__ A, const __half* __restrict__ W,
                  const float* __restrict__ bias, const float* __restrict__ res,
                  void* __restrict__ Cout, int Kp, int N, int Mreal, int resStride) {
    extern __shared__ __half smem[];
    __half* sAb = smem;             // 3 * STG
    __half* sBb = smem + 3 * STG;   // 3 * STG

    int tid = threadIdx.x, lane = tid & 31, warp = tid >> 5;
    int m0 = blockIdx.y * 128, n0 = blockIdx.x * 128;
    int wm = (warp >> 2) * 64, wn = (warp & 3) * 32;
    int lrow = tid >> 2, lko = (tid & 3) << 3;

    float acc[4][4][4];
#pragma unroll
    for (int i = 0; i < 4; i++)
#pragma unroll
        for (int j = 0; j < 4; j++)
#pragma unroll
            for (int e = 0; e < 4; e++) acc[i][j][e] = 0.f;

    auto load_stage = [&](int st, int k0) {
        __half* a = sAb + st * STG;
        __half* b = sBb + st * STG;
        cp16(a + lrow * SKS + lko,        A + (size_t)(m0 + lrow) * Kp + k0 + lko);
        cp16(a + (lrow + 64) * SKS + lko, A + (size_t)(m0 + lrow + 64) * Kp + k0 + lko);
        cp16(b + lrow * SKS + lko,        W + (size_t)(n0 + lrow) * Kp + k0 + lko);
        cp16(b + (lrow + 64) * SKS + lko, W + (size_t)(n0 + lrow + 64) * Kp + k0 + lko);
        asm volatile("cp.async.commit_group;\n" ::: "memory");
    };

    int nk = Kp / BKt;
    load_stage(0, 0);
    load_stage(1, BKt);

    int cs = 0, ls = 2;
    for (int t = 0; t < nk; t++) {
        if (t + 1 < nk) asm volatile("cp.async.wait_group 1;\n" ::: "memory");
        else            asm volatile("cp.async.wait_group 0;\n" ::: "memory");
        __syncthreads();
        if (t + 2 < nk) load_stage(ls, (t + 2) * BKt);
        ls = (ls == 2) ? 0 : ls + 1;

        const __half* as = sAb + cs * STG;
        const __half* bs = sBb + cs * STG;
        cs = (cs == 2) ? 0 : cs + 1;
#pragma unroll
        for (int kk = 0; kk < 2; kk++) {
            int kof = kk * 16 + ((lane >> 4) << 3);
            int rrow = lane & 15;
            unsigned ar[4][4];
#pragma unroll
            for (int mi = 0; mi < 4; mi++)
                ldm4(ar[mi], &as[(wm + mi * 16 + rrow) * SKS + kof]);
            unsigned br[2][4];
#pragma unroll
            for (int p = 0; p < 2; p++)
                ldm4(br[p], &bs[(wn + p * 16 + rrow) * SKS + kof]);
#pragma unroll
            for (int mi = 0; mi < 4; mi++)
#pragma unroll
                for (int nj = 0; nj < 4; nj++)
                    mma16816(acc[mi][nj], ar[mi], br[nj >> 1][nj & 1], br[nj >> 1][(nj & 1) + 2]);
        }
        // single top barrier per iter protects stage reuse
    }

    // epilogue (registers -> global)
    int group = lane >> 2, tig = lane & 3;
#pragma unroll
    for (int mi = 0; mi < 4; mi++) {
#pragma unroll
        for (int nj = 0; nj < 4; nj++) {
            int col = n0 + wn + nj * 8 + tig * 2;
            float bx = 0.f, by = 0.f;
            if (bias) { bx = bias[col]; by = bias[col + 1]; }
#pragma unroll
            for (int h = 0; h < 2; h++) {
                int row = m0 + wm + mi * 16 + group + h * 8;
                if (row >= Mreal) continue;
                float c0 = acc[mi][nj][h * 2 + 0] + bx;
                float c1 = acc[mi][nj][h * 2 + 1] + by;
                if (MODE == 2) {
                    float2 rr = *(const float2*)(res + (size_t)row * resStride + col);
                    c0 += rr.x; c1 += rr.y;
                }
                if (MODE == 3) {
                    __half2 hp;
                    hp.x = __float2half(qgelu(c0));
                    hp.y = __float2half(qgelu(c1));
                    *(__half2*)((__half*)Cout + (size_t)row * N + col) = hp;
                } else {
                    *(float2*)((float*)Cout + (size_t)row * N + col) = make_float2(c0, c1);
                }
            }
        }
    }
}

// ---------------- fused attention v2: half2 K/V, 2 queries per warp iteration ------------
// smem: sK half2[205*33] | sV half2[205*33] | sQ float[8][2][64] | sP float[8][2][208]
#define KVS 33
#define ATTN_SMEM_BYTES ((2*STOK*KVS)*4 + (8*2*64)*4 + (8*2*208)*4)   // 71528
__global__ __launch_bounds__(256)
void attn_kernel(const float* __restrict__ qkv, __half* __restrict__ o) {
    extern __shared__ char asmem[];
    __half2* sK = (__half2*)asmem;
    __half2* sV = sK + STOK * KVS;
    float* sQall = (float*)(sV + STOK * KVS);
    float* sPall = sQall + 8 * 128;
    int bh = blockIdx.x;
    int b = bh / Hn, hh = bh % Hn;
    int tid = threadIdx.x;
    size_t base = (size_t)b * STOK * NQKV + (size_t)hh * DHd;

    // load K, V -> half2 smem
    for (int idx = tid; idx < STOK * 32; idx += 256) {
        int j = idx >> 5, d2 = idx & 31;
        const float* kp = qkv + base + (size_t)j * NQKV + 768 + 2 * d2;
        const float* vp = qkv + base + (size_t)j * NQKV + 1536 + 2 * d2;
        float2 kk = *(const float2*)kp;
        float2 vv = *(const float2*)vp;
        sK[j * KVS + d2] = __floats2half2_rn(kk.x, kk.y);
        sV[j * KVS + d2] = __floats2half2_rn(vv.x, vv.y);
    }
    __syncthreads();

    int warp = tid >> 5, lane = tid & 31;
    float* sQ = sQall + warp * 128;   // [2][64]
    float* sP = sPall + warp * 416;   // [2][208]

    for (int i0 = warp * 2; i0 < STOK; i0 += 16) {
        // load up to 2 queries into smem (fp32, broadcast-read later)
#pragma unroll
        for (int qq = 0; qq < 2; qq++) {
            int i = i0 + qq;
            if (i < STOK) {
                const float* qr = qkv + base + (size_t)i * NQKV;
                sQ[qq * 64 + lane]      = qr[lane];
                sQ[qq * 64 + lane + 32] = qr[lane + 32];
            }
        }
        __syncwarp();

        float e0[7], e1[7];
        float mx0 = -1e30f, mx1 = -1e30f;
#pragma unroll
        for (int jj = 0; jj < 7; jj++) {
            int j = lane + jj * 32;
            float s0 = -1e30f, s1 = -1e30f;
            if (j < STOK) {
                s0 = 0.f; s1 = 0.f;
                const __half2* kr = sK + j * KVS;
#pragma unroll
                for (int d2 = 0; d2 < 32; d2++) {
                    float2 kf = __half22float2(kr[d2]);
                    s0 += kf.x * sQ[2 * d2]      + kf.y * sQ[2 * d2 + 1];
                    s1 += kf.x * sQ[64 + 2 * d2] + kf.y * sQ[64 + 2 * d2 + 1];
                }
            }
            e0[jj] = s0; e1[jj] = s1;
            mx0 = fmaxf(mx0, s0); mx1 = fmaxf(mx1, s1);
        }
#pragma unroll
        for (int off = 16; off; off >>= 1) {
            mx0 = fmaxf(mx0, __shfl_xor_sync(0xffffffffu, mx0, off));
            mx1 = fmaxf(mx1, __shfl_xor_sync(0xffffffffu, mx1, off));
        }
        float sum0 = 0.f, sum1 = 0.f;
#pragma unroll
        for (int jj = 0; jj < 7; jj++) {
            int j = lane + jj * 32;
            float v0 = (j < STOK) ? expf(e0[jj] - mx0) : 0.f;
            float v1 = (j < STOK) ? expf(e1[jj] - mx1) : 0.f;
            e0[jj] = v0; e1[jj] = v1;
            sum0 += v0; sum1 += v1;
        }
#pragma unroll
        for (int off = 16; off; off >>= 1) {
            sum0 += __shfl_xor_sync(0xffffffffu, sum0, off);
            sum1 += __shfl_xor_sync(0xffffffffu, sum1, off);
        }
        float inv0 = 1.f / sum0;
        float inv1 = 1.f / sum1;

#pragma unroll
        for (int jj = 0; jj < 7; jj++) {
            int j = lane + jj * 32;
            if (j < STOK) {
                sP[j]       = e0[jj];
                sP[208 + j] = e1[jj];
            }
        }
        __syncwarp();

        // PV: each lane owns dim pair (2*lane, 2*lane+1) for both queries
        float o00 = 0.f, o01 = 0.f, o10 = 0.f, o11 = 0.f;
        const float* p0 = sP;
        const float* p1 = sP + 208;
#pragma unroll 5
        for (int j = 0; j < STOK; j++) {
            float2 vf = __half22float2(sV[j * KVS + lane]);
            float w0 = p0[j], w1 = p1[j];
            o00 += w0 * vf.x; o01 += w0 * vf.y;
            o10 += w1 * vf.x; o11 += w1 * vf.y;
        }
        __half2* orow0 = (__half2*)(o + (size_t)(b * STOK + i0) * Dm + hh * DHd) + lane;
        *orow0 = __floats2half2_rn(o00 * inv0, o01 * inv0);
        if (i0 + 1 < STOK) {
            __half2* orow1 = (__half2*)(o + (size_t)(b * STOK + i0 + 1) * Dm + hh * DHd) + lane;
            *orow1 = __floats2half2_rn(o10 * inv1, o11 * inv1);
        }
        __syncwarp();
    }
}

// ---------------- host orchestration ----------------
extern "C" void kernel_launch(void* const* d_in, const int* in_sizes, int n_in,
                              void* d_out, int out_size) {
    const float* image   = (const float*)d_in[0];
    const float* gprompt = (const float*)d_in[1];
    const float* patch_w = (const float*)d_in[2];
    const float* cls_emb = (const float*)d_in[3];
    const float* pos_emb = (const float*)d_in[4];
    const float* pre_g   = (const float*)d_in[5];
    const float* pre_b   = (const float*)d_in[6];
    const float* ln1_g   = (const float*)d_in[7];
    const float* ln1_b   = (const float*)d_in[8];
    const float* qw      = (const float*)d_in[9];
    const float* qb      = (const float*)d_in[10];
    const float* kw      = (const float*)d_in[11];
    const float* kb      = (const float*)d_in[12];
    const float* vw      = (const float*)d_in[13];
    const float* vb      = (const float*)d_in[14];
    const float* ow      = (const float*)d_in[15];
    const float* ob      = (const float*)d_in[16];
    const float* ln2_g   = (const float*)d_in[17];
    const float* ln2_b   = (const float*)d_in[18];
    const float* fc1_w   = (const float*)d_in[19];
    const float* fc1_b   = (const float*)d_in[20];
    const float* fc2_w   = (const float*)d_in[21];
    const float* fc2_b   = (const float*)d_in[22];
    const float* post_g  = (const float*)d_in[23];
    const float* post_b  = (const float*)d_in[24];
    float* out = (float*)d_out;

    float *x, *qkv, *bqkv;
    __half *ae1, *ae2, *wqkvd, *wod, *w1d, *w2d, *wpd;
    cudaGetSymbolAddress((void**)&x,    g_x);
    cudaGetSymbolAddress((void**)&qkv,  g_qkv);
    cudaGetSymbolAddress((void**)&bqkv, g_bqkv);
    cudaGetSymbolAddress((void**)&ae1,  g_ae1);
    cudaGetSymbolAddress((void**)&ae2,  g_ae2);
    cudaGetSymbolAddress((void**)&wqkvd, g_wqkv);
    cudaGetSymbolAddress((void**)&wod,  g_wo);
    cudaGetSymbolAddress((void**)&w1d,  g_w1);
    cudaGetSymbolAddress((void**)&w2d,  g_w2);
    cudaGetSymbolAddress((void**)&wpd,  g_wp);

    cudaFuncSetAttribute(attn_kernel, cudaFuncAttributeMaxDynamicSharedMemorySize, ATTN_SMEM_BYTES);
    cudaFuncSetAttribute(bgemm_kernel<0>, cudaFuncAttributeMaxDynamicSharedMemorySize, GSM);
    cudaFuncSetAttribute(bgemm_kernel<2>, cudaFuncAttributeMaxDynamicSharedMemorySize, GSM);
    cudaFuncSetAttribute(bgemm_kernel<3>, cudaFuncAttributeMaxDynamicSharedMemorySize, GSM);

    // --- preamble; position #4 (1-based) = conv GEMM for ncu capture ---
    {
        long long n;
        n = (long long)Dm * Dm;                                            // 1
        wconv_kernel<<<(unsigned)((n + 255) / 256), 256>>>(patch_w, wpd, n);
        im2col_kernel<<<(MPATCH * Dm + 255) / 256, 256>>>(image, ae1);      // 2
        bconv_qkv_kernel<<<(Lnum * NQKV + 255) / 256, 256>>>(qb, kb, vb, bqkv); // 3
        // 4: conv GEMM  <- ncu capture target
        bgemm_kernel<0><<<dim3(Dm / 128, MPATCH / 128), 256, GSM>>>(
            ae1, wpd, nullptr, nullptr, qkv, Dm, Dm, MPATCH, 0);
        n = (long long)Lnum * NQKV * Dm;                                    // 5
        wconv_qkv_kernel<<<(unsigned)((n + 255) / 256), 256>>>(qw, kw, vw, wqkvd);
        assemble_kernel<<<(MTOK * Dm + 255) / 256, 256>>>(qkv, cls_emb, pos_emb, gprompt, x); // 6
        ln_kernel<0><<<MTOK, 256>>>(x, pre_g, pre_b, x, Dm, Dm);            // 7
        n = (long long)Lnum * Dm * Dm;                                      // 8
        wconv_kernel<<<(unsigned)((n + 255) / 256), 256>>>(ow, wod, n);
        n = (long long)Lnum * FFd * Dm;                                     // 9
        wconv_kernel<<<(unsigned)((n + 255) / 256), 256>>>(fc1_w, w1d, n);
        n = (long long)Lnum * Dm * FFd;                                     // 10
        wconv_kernel<<<(unsigned)((n + 255) / 256), 256>>>(fc2_w, w2d, n);
    }

    dim3 g768(Dm / 128, MPAD / 128);    // (6, 103)
    dim3 gqkv(NQKV / 128, MPAD / 128);  // (18, 103)
    dim3 gff(FFd / 128, MPAD / 128);    // (24, 103)

    for (int l = 0; l < Lnum; l++) {
        if (l > 0) {
            int tot = Bsz * NPRn * Dm;
            replace_kernel<<<(tot + 255) / 256, 256>>>(x, gprompt, l);
        }
        // attention
        ln_kernel<1><<<MTOK, 256>>>(x, ln1_g + (size_t)l * Dm, ln1_b + (size_t)l * Dm, ae1, Dm, 0);
        bgemm_kernel<0><<<gqkv, 256, GSM>>>(
            ae1, wqkvd + (size_t)l * NQKV * Dm, bqkv + (size_t)l * NQKV,
            nullptr, qkv, Dm, NQKV, MTOK, 0);
        attn_kernel<<<Bsz * Hn, 256, ATTN_SMEM_BYTES>>>(qkv, ae1);
        bgemm_kernel<2><<<g768, 256, GSM>>>(
            ae1, wod + (size_t)l * Dm * Dm, ob + (size_t)l * Dm,
            x, x, Dm, Dm, MTOK, Dm);
        // MLP
        ln_kernel<1><<<MTOK, 256>>>(x, ln2_g + (size_t)l * Dm, ln2_b + (size_t)l * Dm, ae1, Dm, 0);
        bgemm_kernel<3><<<gff, 256, GSM>>>(
            ae1, w1d + (size_t)l * FFd * Dm, fc1_b + (size_t)l * FFd,
            nullptr, ae2, Dm, FFd, MTOK, 0);
        bgemm_kernel<2><<<g768, 256, GSM>>>(
            ae2, w2d + (size_t)l * Dm * FFd, fc2_b + (size_t)l * Dm,
            x, x, FFd, Dm, MTOK, Dm);
    }

    ln_kernel<0><<<Bsz, 256>>>(x, post_g, post_b, out, STOK * Dm, Dm);
}

// round 12
// speedup vs baseline: 3.5786x; 1.4907x over previous
#include <cuda_runtime.h>
#include <cuda_fp16.h>
#include <math.h>
#include <stdint.h>

// ---------------- problem constants ----------------
#define Bsz    64
#define Dm     768
#define Hn     12
#define DHd    64
#define Lnum   12
#define FFd    3072
#define NPRn   8
#define STOK   205
#define NPATCH 196
#define MTOK   (Bsz*STOK)     // 13120
#define MPATCH (Bsz*NPATCH)   // 12544 = 98*128
#define MPAD   13184          // 103*128 >= MTOK
#define NQKV   2304           // fused q|k|v output width

// ---------------- static device scratch ----------------
__device__ float g_x[MPAD*Dm];
__device__ float g_qkv[(size_t)MPAD*NQKV];        // packed q|k|v fp32
__device__ float  g_bqkv[(size_t)Lnum*NQKV];
__device__ __half g_ae1[(size_t)MPAD*Dm];         // fp16 activations (K=768 GEMMs)
__device__ __half g_ae2[(size_t)MPAD*FFd];        // fp16 MLP hidden
__device__ __half g_wqkv[(size_t)Lnum*NQKV*Dm];
__device__ __half g_wo[(size_t)Lnum*Dm*Dm];
__device__ __half g_w1[(size_t)Lnum*FFd*Dm];
__device__ __half g_w2[(size_t)Lnum*Dm*FFd];
__device__ __half g_wp[(size_t)Dm*Dm];

// ---------------- helpers ----------------
__device__ __forceinline__ float qgelu(float x) {
    return x / (1.f + expf(-1.702f * x));
}
__device__ __forceinline__ void cp16(void* s, const void* g) {
    unsigned sa = (unsigned)__cvta_generic_to_shared(s);
    asm volatile("cp.async.ca.shared.global [%0], [%1], 16;\n" :: "r"(sa), "l"(g));
}
__device__ __forceinline__ void ldm4(unsigned* r, const __half* p) {
    unsigned s = (unsigned)__cvta_generic_to_shared(p);
    asm volatile("ldmatrix.sync.aligned.m8n8.x4.shared.b16 {%0,%1,%2,%3}, [%4];"
                 : "=r"(r[0]), "=r"(r[1]), "=r"(r[2]), "=r"(r[3]) : "r"(s));
}
__device__ __forceinline__ void mma16816(float* d, const unsigned* a, unsigned b0, unsigned b1) {
    asm volatile("mma.sync.aligned.m16n8k16.row.col.f32.f16.f16.f32 "
                 "{%0,%1,%2,%3}, {%4,%5,%6,%7}, {%8,%9}, {%0,%1,%2,%3};"
                 : "+f"(d[0]), "+f"(d[1]), "+f"(d[2]), "+f"(d[3])
                 : "r"(a[0]), "r"(a[1]), "r"(a[2]), "r"(a[3]), "r"(b0), "r"(b1));
}
__device__ __forceinline__ unsigned packh2(float a, float b) {
    __half2 h = __floats2half2_rn(a, b);
    return *(unsigned*)&h;
}

// ---------------- weight conversion: fp32 -> fp16, same layout ----------------
__global__ __launch_bounds__(256) void wconv_kernel(const float* __restrict__ src,
                                                    __half* __restrict__ dst,
                                                    long long total) {
    long long idx = (long long)blockIdx.x * 256 + threadIdx.x;
    if (idx >= total) return;
    dst[idx] = __float2half(src[idx]);
}

// ---------------- fused QKV weight conversion (scale folded into q rows) ----------------
__global__ __launch_bounds__(256) void wconv_qkv_kernel(const float* __restrict__ qw,
                                                        const float* __restrict__ kw,
                                                        const float* __restrict__ vw,
                                                        __half* __restrict__ dst) {
    long long idx = (long long)blockIdx.x * 256 + threadIdx.x;
    if (idx >= (long long)Lnum * NQKV * Dm) return;
    int k = (int)(idx % Dm);
    long long rowall = idx / Dm;
    int rr = (int)(rowall % NQKV);
    int l  = (int)(rowall / NQKV);
    float w;
    if (rr < 768)        w = qw[((size_t)l * Dm + rr) * Dm + k] * 0.125f;
    else if (rr < 1536)  w = kw[((size_t)l * Dm + (rr - 768)) * Dm + k];
    else                 w = vw[((size_t)l * Dm + (rr - 1536)) * Dm + k];
    dst[idx] = __float2half(w);
}

__global__ __launch_bounds__(256) void bconv_qkv_kernel(const float* __restrict__ qb,
                                                        const float* __restrict__ kb,
                                                        const float* __restrict__ vb,
                                                        float* __restrict__ out) {
    int idx = blockIdx.x * 256 + threadIdx.x;
    if (idx >= Lnum * NQKV) return;
    int rr = idx % NQKV, l = idx / NQKV;
    float v;
    if (rr < 768)       v = qb[l * Dm + rr] * 0.125f;
    else if (rr < 1536) v = kb[l * Dm + (rr - 768)];
    else                v = vb[l * Dm + (rr - 1536)];
    out[idx] = v;
}

// ---------------- im2col fp16: image -> ae1 [MPATCH, 768] ----------------
__global__ __launch_bounds__(256) void im2col_kernel(const float* __restrict__ img,
                                                     __half* __restrict__ out) {
    int idx = blockIdx.x * 256 + threadIdx.x;
    if (idx >= MPATCH * Dm) return;
    int k = idx % Dm;
    int m = idx / Dm;
    int b = m / NPATCH, p = m % NPATCH;
    int py = p / 14, px = p % 14;
    int c = k >> 8, i = (k >> 4) & 15, j = k & 15;
    out[idx] = __float2half(
        img[(((size_t)b * 3 + c) * 224 + (py * 16 + i)) * 224 + (px * 16 + j)]);
}

// ---------------- assemble / replace ----------------
__global__ __launch_bounds__(256) void assemble_kernel(const float* __restrict__ feat,
                                                       const float* __restrict__ cls,
                                                       const float* __restrict__ pos,
                                                       const float* __restrict__ gp,
                                                       float* __restrict__ x) {
    int idx = blockIdx.x * blockDim.x + threadIdx.x;
    if (idx >= MTOK * Dm) return;
    int d = idx % Dm;
    int s = (idx / Dm) % STOK;
    int b = idx / (Dm * STOK);
    float v;
    if (s == 0)       v = cls[d] + pos[d];
    else if (s < 197) v = feat[((size_t)(b * NPATCH + s - 1)) * Dm + d] + pos[(size_t)s * Dm + d];
    else              v = gp[(((size_t)b * Lnum + 0) * NPRn + (s - 197)) * Dm + d];
    x[idx] = v;
}

__global__ __launch_bounds__(256) void replace_kernel(float* __restrict__ x,
                                                      const float* __restrict__ gp,
                                                      int layer) {
    int idx = blockIdx.x * blockDim.x + threadIdx.x;
    if (idx >= Bsz * NPRn * Dm) return;
    int d = idx % Dm;
    int r = (idx / Dm) % NPRn;
    int b = idx / (Dm * NPRn);
    x[((size_t)(b * STOK + 197 + r)) * Dm + d] =
        gp[(((size_t)b * Lnum + layer) * NPRn + r) * Dm + d];
}

// ---------------- LayerNorm: EXPOUT=0 fp32 out, EXPOUT=1 fp16 out (stride 768) ----------
template <int EXPOUT>
__global__ __launch_bounds__(256) void ln_kernel(const float* __restrict__ x,
                                                 const float* __restrict__ g,
                                                 const float* __restrict__ bb,
                                                 void* __restrict__ outp,
                                                 int in_stride, int out_stride) {
    const float* xr = x + (size_t)blockIdx.x * in_stride;
    int t = threadIdx.x;
    float v0 = xr[t], v1 = xr[t + 256], v2 = xr[t + 512];
    float s = v0 + v1 + v2;
    float q = v0 * v0 + v1 * v1 + v2 * v2;
#pragma unroll
    for (int off = 16; off; off >>= 1) {
        s += __shfl_xor_sync(0xffffffffu, s, off);
        q += __shfl_xor_sync(0xffffffffu, q, off);
    }
    __shared__ float ws[8], wq[8], stat[2];
    int w = t >> 5, lane = t & 31;
    if (lane == 0) { ws[w] = s; wq[w] = q; }
    __syncthreads();
    if (t < 32) {
        float s2 = (t < 8) ? ws[t] : 0.f;
        float q2 = (t < 8) ? wq[t] : 0.f;
#pragma unroll
        for (int off = 4; off; off >>= 1) {
            s2 += __shfl_xor_sync(0xffffffffu, s2, off);
            q2 += __shfl_xor_sync(0xffffffffu, q2, off);
        }
        if (t == 0) {
            float mean = s2 * (1.f / 768.f);
            float var  = q2 * (1.f / 768.f) - mean * mean;
            stat[0] = mean;
            stat[1] = rsqrtf(var + 1e-5f);
        }
    }
    __syncthreads();
    float mean = stat[0], inv = stat[1];
    float y0 = (v0 - mean) * inv * g[t]       + bb[t];
    float y1 = (v1 - mean) * inv * g[t + 256] + bb[t + 256];
    float y2 = (v2 - mean) * inv * g[t + 512] + bb[t + 512];
    if (EXPOUT) {
        __half* o = (__half*)outp + (size_t)blockIdx.x * Dm;
        o[t]       = __float2half(y0);
        o[t + 256] = __float2half(y1);
        o[t + 512] = __float2half(y2);
    } else {
        float* o = (float*)outp + (size_t)blockIdx.x * out_stride;
        o[t] = y0; o[t + 256] = y1; o[t + 512] = y2;
    }
}

// ======== fp16 HMMA GEMM (R5-proven config): C[M,N] = A[M,Kp] @ W[N,Kp]^T ========
// BM=128, BN=128, warp 64x32, 256 thr, 2 CTA/SM, 3-stage cp.async, K-tile 32.
// MODE 0: +bias fp32 out; 2: +bias+res fp32 out; 3: quick_gelu(+bias) -> fp16 out
#define BKt 32
#define SKS 40   // padded K stride in fp16 (80B rows)
#define STG (128*SKS)
#define GSM (6*STG*2)    // 61440 bytes

template <int MODE>
__global__ __launch_bounds__(256, 2)
void bgemm_kernel(const __half* __restrict__ A, const __half* __restrict__ W,
                  const float* __restrict__ bias, const float* __restrict__ res,
                  void* __restrict__ Cout, int Kp, int N, int Mreal, int resStride) {
    extern __shared__ __half smem[];
    __half* sAb = smem;             // 3 * STG
    __half* sBb = smem + 3 * STG;   // 3 * STG

    int tid = threadIdx.x, lane = tid & 31, warp = tid >> 5;
    int m0 = blockIdx.y * 128, n0 = blockIdx.x * 128;
    int wm = (warp >> 2) * 64, wn = (warp & 3) * 32;
    int lrow = tid >> 2, lko = (tid & 3) << 3;

    float acc[4][4][4];
#pragma unroll
    for (int i = 0; i < 4; i++)
#pragma unroll
        for (int j = 0; j < 4; j++)
#pragma unroll
            for (int e = 0; e < 4; e++) acc[i][j][e] = 0.f;

    auto load_stage = [&](int st, int k0) {
        __half* a = sAb + st * STG;
        __half* b = sBb + st * STG;
        cp16(a + lrow * SKS + lko,        A + (size_t)(m0 + lrow) * Kp + k0 + lko);
        cp16(a + (lrow + 64) * SKS + lko, A + (size_t)(m0 + lrow + 64) * Kp + k0 + lko);
        cp16(b + lrow * SKS + lko,        W + (size_t)(n0 + lrow) * Kp + k0 + lko);
        cp16(b + (lrow + 64) * SKS + lko, W + (size_t)(n0 + lrow + 64) * Kp + k0 + lko);
        asm volatile("cp.async.commit_group;\n" ::: "memory");
    };

    int nk = Kp / BKt;
    load_stage(0, 0);
    load_stage(1, BKt);

    int cs = 0, ls = 2;
    for (int t = 0; t < nk; t++) {
        if (t + 1 < nk) asm volatile("cp.async.wait_group 1;\n" ::: "memory");
        else            asm volatile("cp.async.wait_group 0;\n" ::: "memory");
        __syncthreads();
        if (t + 2 < nk) load_stage(ls, (t + 2) * BKt);
        ls = (ls == 2) ? 0 : ls + 1;

        const __half* as = sAb + cs * STG;
        const __half* bs = sBb + cs * STG;
        cs = (cs == 2) ? 0 : cs + 1;
#pragma unroll
        for (int kk = 0; kk < 2; kk++) {
            int kof = kk * 16 + ((lane >> 4) << 3);
            int rrow = lane & 15;
            unsigned ar[4][4];
#pragma unroll
            for (int mi = 0; mi < 4; mi++)
                ldm4(ar[mi], &as[(wm + mi * 16 + rrow) * SKS + kof]);
            unsigned br[2][4];
#pragma unroll
            for (int p = 0; p < 2; p++)
                ldm4(br[p], &bs[(wn + p * 16 + rrow) * SKS + kof]);
#pragma unroll
            for (int mi = 0; mi < 4; mi++)
#pragma unroll
                for (int nj = 0; nj < 4; nj++)
                    mma16816(acc[mi][nj], ar[mi], br[nj >> 1][nj & 1], br[nj >> 1][(nj & 1) + 2]);
        }
    }

    // epilogue (registers -> global)
    int group = lane >> 2, tig = lane & 3;
#pragma unroll
    for (int mi = 0; mi < 4; mi++) {
#pragma unroll
        for (int nj = 0; nj < 4; nj++) {
            int col = n0 + wn + nj * 8 + tig * 2;
            float bx = 0.f, by = 0.f;
            if (bias) { bx = bias[col]; by = bias[col + 1]; }
#pragma unroll
            for (int h = 0; h < 2; h++) {
                int row = m0 + wm + mi * 16 + group + h * 8;
                if (row >= Mreal) continue;
                float c0 = acc[mi][nj][h * 2 + 0] + bx;
                float c1 = acc[mi][nj][h * 2 + 1] + by;
                if (MODE == 2) {
                    float2 rr = *(const float2*)(res + (size_t)row * resStride + col);
                    c0 += rr.x; c1 += rr.y;
                }
                if (MODE == 3) {
                    __half2 hp;
                    hp.x = __float2half(qgelu(c0));
                    hp.y = __float2half(qgelu(c1));
                    *(__half2*)((__half*)Cout + (size_t)row * N + col) = hp;
                } else {
                    *(float2*)((float*)Cout + (size_t)row * N + col) = make_float2(c0, c1);
                }
            }
        }
    }
}

// ======== tensor-core attention: one block per (b,h); Q,K,V fp16 in smem; mma QK + PV =====
// smem: sQ[208][72] | sK[208][72] | sVT[64][216]  (halfs)
#define QS 72
#define VTS 216
#define NT 208
#define ATTN_SMEM_BYTES ((NT*QS + NT*QS + 64*VTS)*2)   // 87552
__global__ __launch_bounds__(256, 1)
void attn_kernel(const float* __restrict__ qkv, __half* __restrict__ o) {
    extern __shared__ __half ash[];
    __half* sQ  = ash;
    __half* sK  = sQ + NT * QS;
    __half* sVT = sK + NT * QS;
    int bh = blockIdx.x;
    int b = bh / Hn, hh = bh % Hn;
    int tid = threadIdx.x;
    size_t base = (size_t)b * STOK * NQKV + (size_t)hh * DHd;

    // zero pad token rows 205..207 (Q,K) and pad cols (VT)
    for (int idx = tid; idx < 3 * 32; idx += 256) {
        int r = 205 + idx / 32, d2 = idx % 32;
        *(__half2*)(sQ + r * QS + 2 * d2) = __floats2half2_rn(0.f, 0.f);
        *(__half2*)(sK + r * QS + 2 * d2) = __floats2half2_rn(0.f, 0.f);
    }
    for (int idx = tid; idx < 64 * 3; idx += 256) {
        int d = idx / 3, t = 205 + idx % 3;
        sVT[d * VTS + t] = __float2half(0.f);
    }
    // stage Q, K (row-major) and V transposed
    for (int idx = tid; idx < STOK * 32; idx += 256) {
        int j = idx >> 5, d2 = idx & 31;
        const float* rp = qkv + base + (size_t)j * NQKV + 2 * d2;
        float2 qq = *(const float2*)(rp);
        float2 kk = *(const float2*)(rp + 768);
        float2 vv = *(const float2*)(rp + 1536);
        *(__half2*)(sQ + j * QS + 2 * d2) = __floats2half2_rn(qq.x, qq.y);
        *(__half2*)(sK + j * QS + 2 * d2) = __floats2half2_rn(kk.x, kk.y);
        sVT[(2 * d2) * VTS + j]     = __float2half(vv.x);
        sVT[(2 * d2 + 1) * VTS + j] = __float2half(vv.y);
    }
    __syncthreads();

    int warp = tid >> 5, lane = tid & 31;
    int group = lane >> 2, tig = lane & 3;
    int rrow = lane & 15, khalf = (lane >> 4) << 3;

    for (int qt = warp; qt < 13; qt += 8) {
        // ---- S = Q @ K^T  (16 queries x 208 keys), fp32 accum ----
        float S[26][4];
#pragma unroll
        for (int f = 0; f < 26; f++)
#pragma unroll
            for (int e = 0; e < 4; e++) S[f][e] = 0.f;

#pragma unroll
        for (int kt = 0; kt < 4; kt++) {
            unsigned aq[4];
            ldm4(aq, sQ + (qt * 16 + rrow) * QS + kt * 16 + khalf);
#pragma unroll
            for (int nt = 0; nt < 13; nt++) {
                unsigned kb[4];
                ldm4(kb, sK + (nt * 16 + rrow) * QS + kt * 16 + khalf);
                mma16816(S[2 * nt],     aq, kb[0], kb[2]);
                mma16816(S[2 * nt + 1], aq, kb[1], kb[3]);
            }
        }

        // ---- softmax over keys (mask >=205), P packed to half2 in-register ----
        float mx0 = -1e30f, mx1 = -1e30f;
#pragma unroll
        for (int f = 0; f < 26; f++) {
            int c0 = f * 8 + 2 * tig;
            if (c0 < STOK)     { mx0 = fmaxf(mx0, S[f][0]); mx1 = fmaxf(mx1, S[f][2]); }
            if (c0 + 1 < STOK) { mx0 = fmaxf(mx0, S[f][1]); mx1 = fmaxf(mx1, S[f][3]); }
        }
        mx0 = fmaxf(mx0, __shfl_xor_sync(0xffffffffu, mx0, 1));
        mx0 = fmaxf(mx0, __shfl_xor_sync(0xffffffffu, mx0, 2));
        mx1 = fmaxf(mx1, __shfl_xor_sync(0xffffffffu, mx1, 1));
        mx1 = fmaxf(mx1, __shfl_xor_sync(0xffffffffu, mx1, 2));

        float sum0 = 0.f, sum1 = 0.f;
        unsigned Pg[26], Pg8[26];
#pragma unroll
        for (int f = 0; f < 26; f++) {
            int c0 = f * 8 + 2 * tig;
            float e0 = (c0 < STOK)     ? __expf(S[f][0] - mx0) : 0.f;
            float e1 = (c0 + 1 < STOK) ? __expf(S[f][1] - mx0) : 0.f;
            float e2 = (c0 < STOK)     ? __expf(S[f][2] - mx1) : 0.f;
            float e3 = (c0 + 1 < STOK) ? __expf(S[f][3] - mx1) : 0.f;
            sum0 += e0 + e1;
            sum1 += e2 + e3;
            Pg[f]  = packh2(e0, e1);
            Pg8[f] = packh2(e2, e3);
        }
        sum0 += __shfl_xor_sync(0xffffffffu, sum0, 1);
        sum0 += __shfl_xor_sync(0xffffffffu, sum0, 2);
        sum1 += __shfl_xor_sync(0xffffffffu, sum1, 1);
        sum1 += __shfl_xor_sync(0xffffffffu, sum1, 2);
        float inv0 = 1.f / sum0, inv1 = 1.f / sum1;

        // ---- O = P @ V  (16 x 64), fp32 accum ----
        float O[8][4];
#pragma unroll
        for (int f = 0; f < 8; f++)
#pragma unroll
            for (int e = 0; e < 4; e++) O[f][e] = 0.f;

#pragma unroll
        for (int kt = 0; kt < 13; kt++) {
            unsigned ap[4] = {Pg[2 * kt], Pg8[2 * kt], Pg[2 * kt + 1], Pg8[2 * kt + 1]};
#pragma unroll
            for (int vd = 0; vd < 4; vd++) {
                unsigned vb[4];
                ldm4(vb, sVT + (vd * 16 + rrow) * VTS + kt * 16 + khalf);
                mma16816(O[2 * vd],     ap, vb[0], vb[2]);
                mma16816(O[2 * vd + 1], ap, vb[1], vb[3]);
            }
        }

        // ---- store fp16 output ----
        int q0 = qt * 16 + group;
        int q1 = q0 + 8;
#pragma unroll
        for (int nt = 0; nt < 8; nt++) {
            int col = hh * DHd + nt * 8 + 2 * tig;
            if (q0 < STOK) {
                __half2 hp = __floats2half2_rn(O[nt][0] * inv0, O[nt][1] * inv0);
                *(__half2*)(o + (size_t)(b * STOK + q0) * Dm + col) = hp;
            }
            if (q1 < STOK) {
                __half2 hp = __floats2half2_rn(O[nt][2] * inv1, O[nt][3] * inv1);
                *(__half2*)(o + (size_t)(b * STOK + q1) * Dm + col) = hp;
            }
        }
    }
}

// ---------------- host orchestration ----------------
extern "C" void kernel_launch(void* const* d_in, const int* in_sizes, int n_in,
                              void* d_out, int out_size) {
    const float* image   = (const float*)d_in[0];
    const float* gprompt = (const float*)d_in[1];
    const float* patch_w = (const float*)d_in[2];
    const float* cls_emb = (const float*)d_in[3];
    const float* pos_emb = (const float*)d_in[4];
    const float* pre_g   = (const float*)d_in[5];
    const float* pre_b   = (const float*)d_in[6];
    const float* ln1_g   = (const float*)d_in[7];
    const float* ln1_b   = (const float*)d_in[8];
    const float* qw      = (const float*)d_in[9];
    const float* qb      = (const float*)d_in[10];
    const float* kw      = (const float*)d_in[11];
    const float* kb      = (const float*)d_in[12];
    const float* vw      = (const float*)d_in[13];
    const float* vb      = (const float*)d_in[14];
    const float* ow      = (const float*)d_in[15];
    const float* ob      = (const float*)d_in[16];
    const float* ln2_g   = (const float*)d_in[17];
    const float* ln2_b   = (const float*)d_in[18];
    const float* fc1_w   = (const float*)d_in[19];
    const float* fc1_b   = (const float*)d_in[20];
    const float* fc2_w   = (const float*)d_in[21];
    const float* fc2_b   = (const float*)d_in[22];
    const float* post_g  = (const float*)d_in[23];
    const float* post_b  = (const float*)d_in[24];
    float* out = (float*)d_out;

    float *x, *qkv, *bqkv;
    __half *ae1, *ae2, *wqkvd, *wod, *w1d, *w2d, *wpd;
    cudaGetSymbolAddress((void**)&x,    g_x);
    cudaGetSymbolAddress((void**)&qkv,  g_qkv);
    cudaGetSymbolAddress((void**)&bqkv, g_bqkv);
    cudaGetSymbolAddress((void**)&ae1,  g_ae1);
    cudaGetSymbolAddress((void**)&ae2,  g_ae2);
    cudaGetSymbolAddress((void**)&wqkvd, g_wqkv);
    cudaGetSymbolAddress((void**)&wod,  g_wo);
    cudaGetSymbolAddress((void**)&w1d,  g_w1);
    cudaGetSymbolAddress((void**)&w2d,  g_w2);
    cudaGetSymbolAddress((void**)&wpd,  g_wp);

    cudaFuncSetAttribute(attn_kernel, cudaFuncAttributeMaxDynamicSharedMemorySize, ATTN_SMEM_BYTES);
    cudaFuncSetAttribute(bgemm_kernel<0>, cudaFuncAttributeMaxDynamicSharedMemorySize, GSM);
    cudaFuncSetAttribute(bgemm_kernel<2>, cudaFuncAttributeMaxDynamicSharedMemorySize, GSM);
    cudaFuncSetAttribute(bgemm_kernel<3>, cudaFuncAttributeMaxDynamicSharedMemorySize, GSM);

    // --- preamble; position #4 (1-based) = conv GEMM for ncu capture ---
    {
        long long n;
        n = (long long)Dm * Dm;                                            // 1
        wconv_kernel<<<(unsigned)((n + 255) / 256), 256>>>(patch_w, wpd, n);
        im2col_kernel<<<(MPATCH * Dm + 255) / 256, 256>>>(image, ae1);      // 2
        bconv_qkv_kernel<<<(Lnum * NQKV + 255) / 256, 256>>>(qb, kb, vb, bqkv); // 3
        // 4: conv GEMM  <- ncu capture target
        bgemm_kernel<0><<<dim3(Dm / 128, MPATCH / 128), 256, GSM>>>(
            ae1, wpd, nullptr, nullptr, qkv, Dm, Dm, MPATCH, 0);
        n = (long long)Lnum * NQKV * Dm;                                    // 5
        wconv_qkv_kernel<<<(unsigned)((n + 255) / 256), 256>>>(qw, kw, vw, wqkvd);
        assemble_kernel<<<(MTOK * Dm + 255) / 256, 256>>>(qkv, cls_emb, pos_emb, gprompt, x); // 6
        ln_kernel<0><<<MTOK, 256>>>(x, pre_g, pre_b, x, Dm, Dm);            // 7
        n = (long long)Lnum * Dm * Dm;                                      // 8
        wconv_kernel<<<(unsigned)((n + 255) / 256), 256>>>(ow, wod, n);
        n = (long long)Lnum * FFd * Dm;                                     // 9
        wconv_kernel<<<(unsigned)((n + 255) / 256), 256>>>(fc1_w, w1d, n);
        n = (long long)Lnum * Dm * FFd;                                     // 10
        wconv_kernel<<<(unsigned)((n + 255) / 256), 256>>>(fc2_w, w2d, n);
    }

    dim3 g768(Dm / 128, MPAD / 128);    // (6, 103)
    dim3 gqkv(NQKV / 128, MPAD / 128);  // (18, 103)
    dim3 gff(FFd / 128, MPAD / 128);    // (24, 103)

    for (int l = 0; l < Lnum; l++) {
        if (l > 0) {
            int tot = Bsz * NPRn * Dm;
            replace_kernel<<<(tot + 255) / 256, 256>>>(x, gprompt, l);
        }
        // attention
        ln_kernel<1><<<MTOK, 256>>>(x, ln1_g + (size_t)l * Dm, ln1_b + (size_t)l * Dm, ae1, Dm, 0);
        bgemm_kernel<0><<<gqkv, 256, GSM>>>(
            ae1, wqkvd + (size_t)l * NQKV * Dm, bqkv + (size_t)l * NQKV,
            nullptr, qkv, Dm, NQKV, MTOK, 0);
        attn_kernel<<<Bsz * Hn, 256, ATTN_SMEM_BYTES>>>(qkv, ae1);
        bgemm_kernel<2><<<g768, 256, GSM>>>(
            ae1, wod + (size_t)l * Dm * Dm, ob + (size_t)l * Dm,
            x, x, Dm, Dm, MTOK, Dm);
        // MLP
        ln_kernel<1><<<MTOK, 256>>>(x, ln2_g + (size_t)l * Dm, ln2_b + (size_t)l * Dm, ae1, Dm, 0);
        bgemm_kernel<3><<<gff, 256, GSM>>>(
            ae1, w1d + (size_t)l * FFd * Dm, fc1_b + (size_t)l * FFd,
            nullptr, ae2, Dm, FFd, MTOK, 0);
        bgemm_kernel<2><<<g768, 256, GSM>>>(
            ae2, w2d + (size_t)l * Dm * FFd, fc2_b + (size_t)l * Dm,
            x, x, FFd, Dm, MTOK, Dm);
    }

    ln_kernel<0><<<Bsz, 256>>>(x, post_g, post_b, out, STOK * Dm, Dm);
}

// round 13
// speedup vs baseline: 3.6385x; 1.0167x over previous
#include <cuda_runtime.h>
#include <cuda_fp16.h>
#include <math.h>
#include <stdint.h>

// ---------------- problem constants ----------------
#define Bsz    64
#define Dm     768
#define Hn     12
#define DHd    64
#define Lnum   12
#define FFd    3072
#define NPRn   8
#define STOK   205
#define NPATCH 196
#define MTOK   (Bsz*STOK)     // 13120
#define MPATCH (Bsz*NPATCH)   // 12544 = 98*128
#define MPAD   13184          // 103*128 >= MTOK
#define NQKV   2304           // fused q|k|v output width

// ---------------- static device scratch ----------------
__device__ float  g_x[MPAD*Dm];
__device__ float  g_feat[MPATCH*Dm];              // conv output fp32
__device__ __half g_qkvh[(size_t)MPAD*NQKV];      // packed q|k|v fp16
__device__ float  g_bqkv[(size_t)Lnum*NQKV];
__device__ __half g_ae1[(size_t)MPAD*Dm];         // fp16 activations (K=768 GEMMs)
__device__ __half g_ae2[(size_t)MPAD*FFd];        // fp16 MLP hidden
__device__ __half g_wqkv[(size_t)Lnum*NQKV*Dm];
__device__ __half g_wo[(size_t)Lnum*Dm*Dm];
__device__ __half g_w1[(size_t)Lnum*FFd*Dm];
__device__ __half g_w2[(size_t)Lnum*Dm*FFd];
__device__ __half g_wp[(size_t)Dm*Dm];

// ---------------- helpers ----------------
__device__ __forceinline__ float qgelu(float x) {
    return x / (1.f + expf(-1.702f * x));
}
__device__ __forceinline__ void cp16(void* s, const void* g) {
    unsigned sa = (unsigned)__cvta_generic_to_shared(s);
    asm volatile("cp.async.ca.shared.global [%0], [%1], 16;\n" :: "r"(sa), "l"(g));
}
__device__ __forceinline__ void ldm4(unsigned* r, const __half* p) {
    unsigned s = (unsigned)__cvta_generic_to_shared(p);
    asm volatile("ldmatrix.sync.aligned.m8n8.x4.shared.b16 {%0,%1,%2,%3}, [%4];"
                 : "=r"(r[0]), "=r"(r[1]), "=r"(r[2]), "=r"(r[3]) : "r"(s));
}
__device__ __forceinline__ void mma16816(float* d, const unsigned* a, unsigned b0, unsigned b1) {
    asm volatile("mma.sync.aligned.m16n8k16.row.col.f32.f16.f16.f32 "
                 "{%0,%1,%2,%3}, {%4,%5,%6,%7}, {%8,%9}, {%0,%1,%2,%3};"
                 : "+f"(d[0]), "+f"(d[1]), "+f"(d[2]), "+f"(d[3])
                 : "r"(a[0]), "r"(a[1]), "r"(a[2]), "r"(a[3]), "r"(b0), "r"(b1));
}
__device__ __forceinline__ unsigned packh2(float a, float b) {
    __half2 h = __floats2half2_rn(a, b);
    return *(unsigned*)&h;
}

// ---------------- weight conversion: fp32 -> fp16, same layout ----------------
__global__ __launch_bounds__(256) void wconv_kernel(const float* __restrict__ src,
                                                    __half* __restrict__ dst,
                                                    long long total) {
    long long idx = (long long)blockIdx.x * 256 + threadIdx.x;
    if (idx >= total) return;
    dst[idx] = __float2half(src[idx]);
}

// ---------------- fused QKV weight conversion (scale folded into q rows) ----------------
__global__ __launch_bounds__(256) void wconv_qkv_kernel(const float* __restrict__ qw,
                                                        const float* __restrict__ kw,
                                                        const float* __restrict__ vw,
                                                        __half* __restrict__ dst) {
    long long idx = (long long)blockIdx.x * 256 + threadIdx.x;
    if (idx >= (long long)Lnum * NQKV * Dm) return;
    int k = (int)(idx % Dm);
    long long rowall = idx / Dm;
    int rr = (int)(rowall % NQKV);
    int l  = (int)(rowall / NQKV);
    float w;
    if (rr < 768)        w = qw[((size_t)l * Dm + rr) * Dm + k] * 0.125f;
    else if (rr < 1536)  w = kw[((size_t)l * Dm + (rr - 768)) * Dm + k];
    else                 w = vw[((size_t)l * Dm + (rr - 1536)) * Dm + k];
    dst[idx] = __float2half(w);
}

__global__ __launch_bounds__(256) void bconv_qkv_kernel(const float* __restrict__ qb,
                                                        const float* __restrict__ kb,
                                                        const float* __restrict__ vb,
                                                        float* __restrict__ out) {
    int idx = blockIdx.x * 256 + threadIdx.x;
    if (idx >= Lnum * NQKV) return;
    int rr = idx % NQKV, l = idx / NQKV;
    float v;
    if (rr < 768)       v = qb[l * Dm + rr] * 0.125f;
    else if (rr < 1536) v = kb[l * Dm + (rr - 768)];
    else                v = vb[l * Dm + (rr - 1536)];
    out[idx] = v;
}

// ---------------- im2col fp16: image -> ae1 [MPATCH, 768] ----------------
__global__ __launch_bounds__(256) void im2col_kernel(const float* __restrict__ img,
                                                     __half* __restrict__ out) {
    int idx = blockIdx.x * 256 + threadIdx.x;
    if (idx >= MPATCH * Dm) return;
    int k = idx % Dm;
    int m = idx / Dm;
    int b = m / NPATCH, p = m % NPATCH;
    int py = p / 14, px = p % 14;
    int c = k >> 8, i = (k >> 4) & 15, j = k & 15;
    out[idx] = __float2half(
        img[(((size_t)b * 3 + c) * 224 + (py * 16 + i)) * 224 + (px * 16 + j)]);
}

// ---------------- assemble ----------------
__global__ __launch_bounds__(256) void assemble_kernel(const float* __restrict__ feat,
                                                       const float* __restrict__ cls,
                                                       const float* __restrict__ pos,
                                                       const float* __restrict__ gp,
                                                       float* __restrict__ x) {
    int idx = blockIdx.x * blockDim.x + threadIdx.x;
    if (idx >= MTOK * Dm) return;
    int d = idx % Dm;
    int s = (idx / Dm) % STOK;
    int b = idx / (Dm * STOK);
    float v;
    if (s == 0)       v = cls[d] + pos[d];
    else if (s < 197) v = feat[((size_t)(b * NPATCH + s - 1)) * Dm + d] + pos[(size_t)s * Dm + d];
    else              v = gp[(((size_t)b * Lnum + 0) * NPRn + (s - 197)) * Dm + d];
    x[idx] = v;
}

// ---------------- LayerNorm (fused prompt replacement for ln1 at layer>=1) --------------
// EXPOUT=0: fp32 out (out_stride). EXPOUT=1: fp16 out (stride 768).
// If gp != nullptr && layer>0: rows with s>=197 read the layer's prompt instead of x,
// AND write that raw prompt back into x (residual stream), exactly matching
// reference "replace then LN".
template <int EXPOUT>
__global__ __launch_bounds__(256) void ln_kernel(float* __restrict__ x,
                                                 const float* __restrict__ g,
                                                 const float* __restrict__ bb,
                                                 void* __restrict__ outp,
                                                 int in_stride, int out_stride,
                                                 const float* __restrict__ gp, int layer) {
    int row = blockIdx.x;
    const float* src = x + (size_t)row * in_stride;
    bool isPrompt = false;
    if (EXPOUT && gp != nullptr && layer > 0) {
        int s = row % STOK;
        if (s >= 197) {
            int b = row / STOK;
            src = gp + (((size_t)b * Lnum + layer) * NPRn + (s - 197)) * Dm;
            isPrompt = true;
        }
    }
    int t = threadIdx.x;
    float v0 = src[t], v1 = src[t + 256], v2 = src[t + 512];
    if (isPrompt) {
        float* xr = x + (size_t)row * in_stride;
        xr[t] = v0; xr[t + 256] = v1; xr[t + 512] = v2;
    }
    float s = v0 + v1 + v2;
    float q = v0 * v0 + v1 * v1 + v2 * v2;
#pragma unroll
    for (int off = 16; off; off >>= 1) {
        s += __shfl_xor_sync(0xffffffffu, s, off);
        q += __shfl_xor_sync(0xffffffffu, q, off);
    }
    __shared__ float ws[8], wq[8], stat[2];
    int w = t >> 5, lane = t & 31;
    if (lane == 0) { ws[w] = s; wq[w] = q; }
    __syncthreads();
    if (t < 32) {
        float s2 = (t < 8) ? ws[t] : 0.f;
        float q2 = (t < 8) ? wq[t] : 0.f;
#pragma unroll
        for (int off = 4; off; off >>= 1) {
            s2 += __shfl_xor_sync(0xffffffffu, s2, off);
            q2 += __shfl_xor_sync(0xffffffffu, q2, off);
        }
        if (t == 0) {
            float mean = s2 * (1.f / 768.f);
            float var  = q2 * (1.f / 768.f) - mean * mean;
            stat[0] = mean;
            stat[1] = rsqrtf(var + 1e-5f);
        }
    }
    __syncthreads();
    float mean = stat[0], inv = stat[1];
    float y0 = (v0 - mean) * inv * g[t]       + bb[t];
    float y1 = (v1 - mean) * inv * g[t + 256] + bb[t + 256];
    float y2 = (v2 - mean) * inv * g[t + 512] + bb[t + 512];
    if (EXPOUT) {
        __half* o = (__half*)outp + (size_t)row * Dm;
        o[t]       = __float2half(y0);
        o[t + 256] = __float2half(y1);
        o[t + 512] = __float2half(y2);
    } else {
        float* o = (float*)outp + (size_t)row * out_stride;
        o[t] = y0; o[t + 256] = y1; o[t + 512] = y2;
    }
}

// ======== fp16 HMMA GEMM: C[M,N] = A[M,Kp] @ W[N,Kp]^T ========
// BM=128, BN=128, warp 64x32, 256 thr, 2 CTA/SM, 3-stage cp.async, K-tile 32.
// MODE 0: +bias fp32; 1: +bias fp16; 2: +bias+res fp32; 3: quick_gelu(+bias) fp16
#define BKt 32
#define SKS 40
#define STG (128*SKS)
#define GSM (6*STG*2)    // 61440 bytes

template <int MODE>
__global__ __launch_bounds__(256, 2)
void bgemm_kernel(const __half* __restrict__ A, const __half* __restrict__ W,
                  const float* __restrict__ bias, const float* __restrict__ res,
                  void* __restrict__ Cout, int Kp, int N, int Mreal, int resStride) {
    extern __shared__ __half smem[];
    __half* sAb = smem;
    __half* sBb = smem + 3 * STG;

    int tid = threadIdx.x, lane = tid & 31, warp = tid >> 5;
    int m0 = blockIdx.y * 128, n0 = blockIdx.x * 128;
    int wm = (warp >> 2) * 64, wn = (warp & 3) * 32;
    int lrow = tid >> 2, lko = (tid & 3) << 3;

    const __half* Ag0 = A + (size_t)(m0 + lrow) * Kp + lko;
    const __half* Ag1 = A + (size_t)(m0 + lrow + 64) * Kp + lko;
    const __half* Bg0 = W + (size_t)(n0 + lrow) * Kp + lko;
    const __half* Bg1 = W + (size_t)(n0 + lrow + 64) * Kp + lko;

    float acc[4][4][4];
#pragma unroll
    for (int i = 0; i < 4; i++)
#pragma unroll
        for (int j = 0; j < 4; j++)
#pragma unroll
            for (int e = 0; e < 4; e++) acc[i][j][e] = 0.f;

    auto load_stage = [&](int st, int k0) {
        __half* a = sAb + st * STG + lrow * SKS + lko;
        __half* b = sBb + st * STG + lrow * SKS + lko;
        cp16(a,            Ag0 + k0);
        cp16(a + 64 * SKS, Ag1 + k0);
        cp16(b,            Bg0 + k0);
        cp16(b + 64 * SKS, Bg1 + k0);
        asm volatile("cp.async.commit_group;\n" ::: "memory");
    };

    int nk = Kp / BKt;
    load_stage(0, 0);
    load_stage(1, BKt);

    int cs = 0, ls = 2;
    for (int t = 0; t < nk; t++) {
        if (t + 1 < nk) asm volatile("cp.async.wait_group 1;\n" ::: "memory");
        else            asm volatile("cp.async.wait_group 0;\n" ::: "memory");
        __syncthreads();
        if (t + 2 < nk) load_stage(ls, (t + 2) * BKt);
        ls = (ls == 2) ? 0 : ls + 1;

        const __half* as = sAb + cs * STG;
        const __half* bs = sBb + cs * STG;
        cs = (cs == 2) ? 0 : cs + 1;
#pragma unroll
        for (int kk = 0; kk < 2; kk++) {
            int kof = kk * 16 + ((lane >> 4) << 3);
            int rrow = lane & 15;
            unsigned ar[4][4];
#pragma unroll
            for (int mi = 0; mi < 4; mi++)
                ldm4(ar[mi], &as[(wm + mi * 16 + rrow) * SKS + kof]);
            unsigned br[2][4];
#pragma unroll
            for (int p = 0; p < 2; p++)
                ldm4(br[p], &bs[(wn + p * 16 + rrow) * SKS + kof]);
#pragma unroll
            for (int mi = 0; mi < 4; mi++)
#pragma unroll
                for (int nj = 0; nj < 4; nj++)
                    mma16816(acc[mi][nj], ar[mi], br[nj >> 1][nj & 1], br[nj >> 1][(nj & 1) + 2]);
        }
    }

    int group = lane >> 2, tig = lane & 3;
#pragma unroll
    for (int mi = 0; mi < 4; mi++) {
#pragma unroll
        for (int nj = 0; nj < 4; nj++) {
            int col = n0 + wn + nj * 8 + tig * 2;
            float bx = 0.f, by = 0.f;
            if (bias) { bx = bias[col]; by = bias[col + 1]; }
#pragma unroll
            for (int h = 0; h < 2; h++) {
                int row = m0 + wm + mi * 16 + group + h * 8;
                if (row >= Mreal) continue;
                float c0 = acc[mi][nj][h * 2 + 0] + bx;
                float c1 = acc[mi][nj][h * 2 + 1] + by;
                if (MODE == 2) {
                    float2 rr = *(const float2*)(res + (size_t)row * resStride + col);
                    c0 += rr.x; c1 += rr.y;
                }
                if (MODE == 3) {
                    __half2 hp;
                    hp.x = __float2half(qgelu(c0));
                    hp.y = __float2half(qgelu(c1));
                    *(__half2*)((__half*)Cout + (size_t)row * N + col) = hp;
                } else if (MODE == 1) {
                    __half2 hp;
                    hp.x = __float2half(c0);
                    hp.y = __float2half(c1);
                    *(__half2*)((__half*)Cout + (size_t)row * N + col) = hp;
                } else {
                    *(float2*)((float*)Cout + (size_t)row * N + col) = make_float2(c0, c1);
                }
            }
        }
    }
}

// ======== tensor-core attention: fp16 qkv input; mma QK + PV ========
// smem: sQ[208][72] | sK[208][72] | sVT[64][216]  (halfs)
#define QS 72
#define VTS 216
#define NT 208
#define ATTN_SMEM_BYTES ((NT*QS + NT*QS + 64*VTS)*2)   // 87552
__global__ __launch_bounds__(256, 1)
void attn_kernel(const __half* __restrict__ qkv, __half* __restrict__ o) {
    extern __shared__ __half ash[];
    __half* sQ  = ash;
    __half* sK  = sQ + NT * QS;
    __half* sVT = sK + NT * QS;
    int bh = blockIdx.x;
    int b = bh / Hn, hh = bh % Hn;
    int tid = threadIdx.x;
    size_t base = (size_t)b * STOK * NQKV + (size_t)hh * DHd;

    // zero pad rows/cols
    for (int idx = tid; idx < 3 * 32; idx += 256) {
        int r = 205 + idx / 32, d2 = idx % 32;
        *(__half2*)(sQ + r * QS + 2 * d2) = __floats2half2_rn(0.f, 0.f);
        *(__half2*)(sK + r * QS + 2 * d2) = __floats2half2_rn(0.f, 0.f);
    }
    for (int idx = tid; idx < 64 * 3; idx += 256) {
        int d = idx / 3, t = 205 + idx % 3;
        sVT[d * VTS + t] = __float2half(0.f);
    }
    // stage Q, K (row-major) and V transposed — half2 loads
    for (int idx = tid; idx < STOK * 32; idx += 256) {
        int j = idx >> 5, d2 = idx & 31;
        const __half2* rp = (const __half2*)(qkv + base + (size_t)j * NQKV) + d2;
        __half2 qq = rp[0];
        __half2 kk = rp[384];   // +768 halfs
        __half2 vv = rp[768];   // +1536 halfs
        *(__half2*)(sQ + j * QS + 2 * d2) = qq;
        *(__half2*)(sK + j * QS + 2 * d2) = kk;
        sVT[(2 * d2) * VTS + j]     = __low2half(vv);
        sVT[(2 * d2 + 1) * VTS + j] = __high2half(vv);
    }
    __syncthreads();

    int warp = tid >> 5, lane = tid & 31;
    int group = lane >> 2, tig = lane & 3;
    int rrow = lane & 15, khalf = (lane >> 4) << 3;

    for (int qt = warp; qt < 13; qt += 8) {
        float S[26][4];
#pragma unroll
        for (int f = 0; f < 26; f++)
#pragma unroll
            for (int e = 0; e < 4; e++) S[f][e] = 0.f;

#pragma unroll
        for (int kt = 0; kt < 4; kt++) {
            unsigned aq[4];
            ldm4(aq, sQ + (qt * 16 + rrow) * QS + kt * 16 + khalf);
#pragma unroll
            for (int nt = 0; nt < 13; nt++) {
                unsigned kb[4];
                ldm4(kb, sK + (nt * 16 + rrow) * QS + kt * 16 + khalf);
                mma16816(S[2 * nt],     aq, kb[0], kb[2]);
                mma16816(S[2 * nt + 1], aq, kb[1], kb[3]);
            }
        }

        float mx0 = -1e30f, mx1 = -1e30f;
#pragma unroll
        for (int f = 0; f < 26; f++) {
            int c0 = f * 8 + 2 * tig;
            if (c0 < STOK)     { mx0 = fmaxf(mx0, S[f][0]); mx1 = fmaxf(mx1, S[f][2]); }
            if (c0 + 1 < STOK) { mx0 = fmaxf(mx0, S[f][1]); mx1 = fmaxf(mx1, S[f][3]); }
        }
        mx0 = fmaxf(mx0, __shfl_xor_sync(0xffffffffu, mx0, 1));
        mx0 = fmaxf(mx0, __shfl_xor_sync(0xffffffffu, mx0, 2));
        mx1 = fmaxf(mx1, __shfl_xor_sync(0xffffffffu, mx1, 1));
        mx1 = fmaxf(mx1, __shfl_xor_sync(0xffffffffu, mx1, 2));

        float sum0 = 0.f, sum1 = 0.f;
        unsigned Pg[26], Pg8[26];
#pragma unroll
        for (int f = 0; f < 26; f++) {
            int c0 = f * 8 + 2 * tig;
            float e0 = (c0 < STOK)     ? __expf(S[f][0] - mx0) : 0.f;
            float e1 = (c0 + 1 < STOK) ? __expf(S[f][1] - mx0) : 0.f;
            float e2 = (c0 < STOK)     ? __expf(S[f][2] - mx1) : 0.f;
            float e3 = (c0 + 1 < STOK) ? __expf(S[f][3] - mx1) : 0.f;
            sum0 += e0 + e1;
            sum1 += e2 + e3;
            Pg[f]  = packh2(e0, e1);
            Pg8[f] = packh2(e2, e3);
        }
        sum0 += __shfl_xor_sync(0xffffffffu, sum0, 1);
        sum0 += __shfl_xor_sync(0xffffffffu, sum0, 2);
        sum1 += __shfl_xor_sync(0xffffffffu, sum1, 1);
        sum1 += __shfl_xor_sync(0xffffffffu, sum1, 2);
        float inv0 = 1.f / sum0, inv1 = 1.f / sum1;

        float O[8][4];
#pragma unroll
        for (int f = 0; f < 8; f++)
#pragma unroll
            for (int e = 0; e < 4; e++) O[f][e] = 0.f;

#pragma unroll
        for (int kt = 0; kt < 13; kt++) {
            unsigned ap[4] = {Pg[2 * kt], Pg8[2 * kt], Pg[2 * kt + 1], Pg8[2 * kt + 1]};
#pragma unroll
            for (int vd = 0; vd < 4; vd++) {
                unsigned vb[4];
                ldm4(vb, sVT + (vd * 16 + rrow) * VTS + kt * 16 + khalf);
                mma16816(O[2 * vd],     ap, vb[0], vb[2]);
                mma16816(O[2 * vd + 1], ap, vb[1], vb[3]);
            }
        }

        int q0 = qt * 16 + group;
        int q1 = q0 + 8;
#pragma unroll
        for (int nt = 0; nt < 8; nt++) {
            int col = hh * DHd + nt * 8 + 2 * tig;
            if (q0 < STOK) {
                __half2 hp = __floats2half2_rn(O[nt][0] * inv0, O[nt][1] * inv0);
                *(__half2*)(o + (size_t)(b * STOK + q0) * Dm + col) = hp;
            }
            if (q1 < STOK) {
                __half2 hp = __floats2half2_rn(O[nt][2] * inv1, O[nt][3] * inv1);
                *(__half2*)(o + (size_t)(b * STOK + q1) * Dm + col) = hp;
            }
        }
    }
}

// ---------------- host orchestration ----------------
extern "C" void kernel_launch(void* const* d_in, const int* in_sizes, int n_in,
                              void* d_out, int out_size) {
    const float* image   = (const float*)d_in[0];
    const float* gprompt = (const float*)d_in[1];
    const float* patch_w = (const float*)d_in[2];
    const float* cls_emb = (const float*)d_in[3];
    const float* pos_emb = (const float*)d_in[4];
    const float* pre_g   = (const float*)d_in[5];
    const float* pre_b   = (const float*)d_in[6];
    const float* ln1_g   = (const float*)d_in[7];
    const float* ln1_b   = (const float*)d_in[8];
    const float* qw      = (const float*)d_in[9];
    const float* qb      = (const float*)d_in[10];
    const float* kw      = (const float*)d_in[11];
    const float* kb      = (const float*)d_in[12];
    const float* vw      = (const float*)d_in[13];
    const float* vb      = (const float*)d_in[14];
    const float* ow      = (const float*)d_in[15];
    const float* ob      = (const float*)d_in[16];
    const float* ln2_g   = (const float*)d_in[17];
    const float* ln2_b   = (const float*)d_in[18];
    const float* fc1_w   = (const float*)d_in[19];
    const float* fc1_b   = (const float*)d_in[20];
    const float* fc2_w   = (const float*)d_in[21];
    const float* fc2_b   = (const float*)d_in[22];
    const float* post_g  = (const float*)d_in[23];
    const float* post_b  = (const float*)d_in[24];
    float* out = (float*)d_out;

    float *x, *feat, *bqkv;
    __half *qkvh, *ae1, *ae2, *wqkvd, *wod, *w1d, *w2d, *wpd;
    cudaGetSymbolAddress((void**)&x,    g_x);
    cudaGetSymbolAddress((void**)&feat, g_feat);
    cudaGetSymbolAddress((void**)&qkvh, g_qkvh);
    cudaGetSymbolAddress((void**)&bqkv, g_bqkv);
    cudaGetSymbolAddress((void**)&ae1,  g_ae1);
    cudaGetSymbolAddress((void**)&ae2,  g_ae2);
    cudaGetSymbolAddress((void**)&wqkvd, g_wqkv);
    cudaGetSymbolAddress((void**)&wod,  g_wo);
    cudaGetSymbolAddress((void**)&w1d,  g_w1);
    cudaGetSymbolAddress((void**)&w2d,  g_w2);
    cudaGetSymbolAddress((void**)&wpd,  g_wp);

    cudaFuncSetAttribute(attn_kernel, cudaFuncAttributeMaxDynamicSharedMemorySize, ATTN_SMEM_BYTES);
    cudaFuncSetAttribute(bgemm_kernel<0>, cudaFuncAttributeMaxDynamicSharedMemorySize, GSM);
    cudaFuncSetAttribute(bgemm_kernel<1>, cudaFuncAttributeMaxDynamicSharedMemorySize, GSM);
    cudaFuncSetAttribute(bgemm_kernel<2>, cudaFuncAttributeMaxDynamicSharedMemorySize, GSM);
    cudaFuncSetAttribute(bgemm_kernel<3>, cudaFuncAttributeMaxDynamicSharedMemorySize, GSM);

    // --- preamble; position #4 (1-based) = conv GEMM for ncu capture ---
    {
        long long n;
        n = (long long)Dm * Dm;                                            // 1
        wconv_kernel<<<(unsigned)((n + 255) / 256), 256>>>(patch_w, wpd, n);
        im2col_kernel<<<(MPATCH * Dm + 255) / 256, 256>>>(image, ae1);      // 2
        bconv_qkv_kernel<<<(Lnum * NQKV + 255) / 256, 256>>>(qb, kb, vb, bqkv); // 3
        // 4: conv GEMM  <- ncu capture target
        bgemm_kernel<0><<<dim3(Dm / 128, MPATCH / 128), 256, GSM>>>(
            ae1, wpd, nullptr, nullptr, feat, Dm, Dm, MPATCH, 0);
        n = (long long)Lnum * NQKV * Dm;                                    // 5
        wconv_qkv_kernel<<<(unsigned)((n + 255) / 256), 256>>>(qw, kw, vw, wqkvd);
        assemble_kernel<<<(MTOK * Dm + 255) / 256, 256>>>(feat, cls_emb, pos_emb, gprompt, x); // 6
        ln_kernel<0><<<MTOK, 256>>>(x, pre_g, pre_b, x, Dm, Dm, nullptr, 0); // 7
        n = (long long)Lnum * Dm * Dm;                                      // 8
        wconv_kernel<<<(unsigned)((n + 255) / 256), 256>>>(ow, wod, n);
        n = (long long)Lnum * FFd * Dm;                                     // 9
        wconv_kernel<<<(unsigned)((n + 255) / 256), 256>>>(fc1_w, w1d, n);
        n = (long long)Lnum * Dm * FFd;                                     // 10
        wconv_kernel<<<(unsigned)((n + 255) / 256), 256>>>(fc2_w, w2d, n);
    }

    dim3 g768(Dm / 128, MPAD / 128);    // (6, 103)
    dim3 gqkv(NQKV / 128, MPAD / 128);  // (18, 103)
    dim3 gff(FFd / 128, MPAD / 128);    // (24, 103)

    for (int l = 0; l < Lnum; l++) {
        // attention (ln1 folds the prompt replacement for l>0)
        ln_kernel<1><<<MTOK, 256>>>(x, ln1_g + (size_t)l * Dm, ln1_b + (size_t)l * Dm,
                                    ae1, Dm, 0, gprompt, l);
        bgemm_kernel<1><<<gqkv, 256, GSM>>>(
            ae1, wqkvd + (size_t)l * NQKV * Dm, bqkv + (size_t)l * NQKV,
            nullptr, qkvh, Dm, NQKV, MTOK, 0);
        attn_kernel<<<Bsz * Hn, 256, ATTN_SMEM_BYTES>>>(qkvh, ae1);
        bgemm_kernel<2><<<g768, 256, GSM>>>(
            ae1, wod + (size_t)l * Dm * Dm, ob + (size_t)l * Dm,
            x, x, Dm, Dm, MTOK, Dm);
        // MLP
        ln_kernel<1><<<MTOK, 256>>>(x, ln2_g + (size_t)l * Dm, ln2_b + (size_t)l * Dm,
                                    ae1, Dm, 0, nullptr, 0);
        bgemm_kernel<3><<<gff, 256, GSM>>>(
            ae1, w1d + (size_t)l * FFd * Dm, fc1_b + (size_t)l * FFd,
            nullptr, ae2, Dm, FFd, MTOK, 0);
        bgemm_kernel<2><<<g768, 256, GSM>>>(
            ae2, w2d + (size_t)l * Dm * FFd, fc2_b + (size_t)l * Dm,
            x, x, FFd, Dm, MTOK, Dm);
    }

    ln_kernel<0><<<Bsz, 256>>>(x, post_g, post_b, out, STOK * Dm, Dm, nullptr, 0);
}